// round 1
// baseline (speedup 1.0000x reference)
#include <cuda_runtime.h>

#define BB 16
#define TTOK 256
#define DD 1024
#define HH 16
#define NBLK 6
#define GDIM 300
#define MLPH 2048
#define FFH 4096
#define DH 64
#define NTOK (BB*TTOK)   // 4096

// ---------------- scratch (device globals; no allocation allowed) ----------------
__device__ float g_xe[NTOK*GDIM];
__device__ float g_h1[NTOK*MLPH];
__device__ float g_x [NTOK*DD];
__device__ float g_q [NTOK*DD];
__device__ float g_k [NTOK*DD];
__device__ float g_v [NTOK*DD];
__device__ float g_o [NTOK*DD];
__device__ float g_s [(size_t)BB*HH*TTOK*TTOK];
__device__ float g_ff[(size_t)NTOK*FFH];

// ---------------- embedding gather ----------------
__global__ void embed_gather(const int* __restrict__ ids, const float* __restrict__ emb) {
    int idx = blockIdx.x * blockDim.x + threadIdx.x;
    if (idx >= NTOK * GDIM) return;
    int bt = idx / GDIM;
    int c  = idx - bt * GDIM;
    g_xe[idx] = emb[(long long)ids[bt] * GDIM + c];
}

// ---------------- positional add ----------------
__global__ void add_pos(const float* __restrict__ pos) {
    int idx = blockIdx.x * blockDim.x + threadIdx.x;
    if (idx >= NTOK * DD) return;
    g_x[idx] += pos[idx % (TTOK * DD)];
}

// ---------------- generic SGEMM: C = [relu](A @ W + bias) ----------------
// A: M x K row-major, W: K x N row-major, bias: N. M,N multiples of 128. K arbitrary.
template<bool RELU>
__global__ void __launch_bounds__(256) sgemm(const float* __restrict__ A,
                                             const float* __restrict__ W,
                                             const float* __restrict__ bias,
                                             float* __restrict__ C,
                                             int M, int N, int K) {
    __shared__ float As[8][128];
    __shared__ float Bs[8][128];
    const int tid  = threadIdx.x;
    const int tr   = tid >> 4;        // 0..15
    const int tc   = tid & 15;        // 0..15
    const int aRow = tid >> 1;        // 0..127
    const int aCol = (tid & 1) * 4;   // 0 or 4
    const int bRow = tid >> 5;        // 0..7
    const int bCol = (tid & 31) * 4;  // 0..124

    const float* Ap = A + (size_t)(blockIdx.y * 128) * K;
    const float* Wp = W + blockIdx.x * 128;

    float acc[8][8];
#pragma unroll
    for (int i = 0; i < 8; i++)
#pragma unroll
        for (int j = 0; j < 8; j++) acc[i][j] = 0.f;

    for (int k0 = 0; k0 < K; k0 += 8) {
#pragma unroll
        for (int j = 0; j < 4; j++) {
            int kk = aCol + j;
            As[kk][aRow] = (k0 + kk < K) ? Ap[(size_t)aRow * K + k0 + kk] : 0.f;
        }
        if (k0 + bRow < K) {
            *(float4*)&Bs[bRow][bCol] = *(const float4*)&Wp[(size_t)(k0 + bRow) * N + bCol];
        } else {
            Bs[bRow][bCol]   = 0.f; Bs[bRow][bCol+1] = 0.f;
            Bs[bRow][bCol+2] = 0.f; Bs[bRow][bCol+3] = 0.f;
        }
        __syncthreads();
#pragma unroll
        for (int kk = 0; kk < 8; kk++) {
            float rm[8], rn[8];
            *(float4*)(rm)     = *(float4*)&As[kk][tr * 8];
            *(float4*)(rm + 4) = *(float4*)&As[kk][tr * 8 + 4];
            *(float4*)(rn)     = *(float4*)&Bs[kk][tc * 8];
            *(float4*)(rn + 4) = *(float4*)&Bs[kk][tc * 8 + 4];
#pragma unroll
            for (int i = 0; i < 8; i++)
#pragma unroll
                for (int j = 0; j < 8; j++)
                    acc[i][j] = fmaf(rm[i], rn[j], acc[i][j]);
        }
        __syncthreads();
    }

    const int colBase = blockIdx.x * 128 + tc * 8;
#pragma unroll
    for (int i = 0; i < 8; i++) {
        int row = blockIdx.y * 128 + tr * 8 + i;
#pragma unroll
        for (int j = 0; j < 8; j++) {
            float vv = acc[i][j] + bias[colBase + j];
            if (RELU) vv = fmaxf(vv, 0.f);
            acc[i][j] = vv;
        }
        *(float4*)&C[(size_t)row * N + colBase]     = *(float4*)&acc[i][0];
        *(float4*)&C[(size_t)row * N + colBase + 4] = *(float4*)&acc[i][4];
    }
}

// ---------------- attention scores: S[b,h,q,k] = Q_row . K_row ----------------
// grid (4,4,B*H), block 256. 64x64 tile per block, K-dim = 64 (head dim).
__global__ void __launch_bounds__(256) attn_scores() {
    const int bh = blockIdx.z;
    const int b  = bh >> 4, h = bh & 15;
    const int q0 = blockIdx.y * 64, n0 = blockIdx.x * 64;
    __shared__ float sQ[64][65];
    __shared__ float sK[64][65];
    const int tid = threadIdx.x;
    const float* Qp = g_q + (size_t)b * TTOK * DD + h * DH;
    const float* Kp = g_k + (size_t)b * TTOK * DD + h * DH;
#pragma unroll
    for (int i = 0; i < 16; i++) {
        int e = tid + i * 256;   // 4096 = 64*64
        int r = e >> 6, c = e & 63;
        sQ[r][c] = Qp[(size_t)(q0 + r) * DD + c];
        sK[r][c] = Kp[(size_t)(n0 + r) * DD + c];
    }
    __syncthreads();
    const int tr = tid >> 4, tc = tid & 15;
    float acc[4][4] = {};
#pragma unroll 8
    for (int kk = 0; kk < 64; kk++) {
        float rq[4], rk[4];
#pragma unroll
        for (int i = 0; i < 4; i++) rq[i] = sQ[tr * 4 + i][kk];
#pragma unroll
        for (int j = 0; j < 4; j++) rk[j] = sK[tc * 4 + j][kk];
#pragma unroll
        for (int i = 0; i < 4; i++)
#pragma unroll
            for (int j = 0; j < 4; j++)
                acc[i][j] = fmaf(rq[i], rk[j], acc[i][j]);
    }
    float* Sp = g_s + ((size_t)bh * TTOK + q0) * TTOK + n0;
#pragma unroll
    for (int i = 0; i < 4; i++)
        *(float4*)&Sp[(size_t)(tr * 4 + i) * TTOK + tc * 4] = *(float4*)&acc[i][0];
}

// ---------------- masked softmax, in place on g_s ----------------
// one warp per row of length 256; grid = B*H*T/8, block 256 (8 warps)
__global__ void __launch_bounds__(256) softmax_kernel(const int* __restrict__ smask,
                                                      const int* __restrict__ graph) {
    const int warp = threadIdx.x >> 5, lane = threadIdx.x & 31;
    const int r = blockIdx.x * 8 + warp;          // < B*H*T
    const int b = r >> 12;                        // / (H*T)
    const int q = r & (TTOK - 1);
    float* row = g_s + (size_t)r * TTOK;
    const int* km = smask + b * TTOK;
    const int* gm = graph + ((size_t)b * TTOK + q) * TTOK;
    const float NEGF = -4294967295.0f;

    float v[8];
    float m = -3.4e38f;
#pragma unroll
    for (int j = 0; j < 8; j++) {
        int c = lane + j * 32;
        float s = row[c] * 0.125f;               // 1/sqrt(64)
        if (!(km[c] > 0 && gm[c] > 0)) s = NEGF;
        v[j] = s;
        m = fmaxf(m, s);
    }
#pragma unroll
    for (int off = 16; off >= 1; off >>= 1)
        m = fmaxf(m, __shfl_xor_sync(0xffffffffu, m, off));
    float sum = 0.f;
#pragma unroll
    for (int j = 0; j < 8; j++) {
        v[j] = expf(v[j] - m);                   // all-masked row -> exp(0)=1 each (matches jax)
        sum += v[j];
    }
#pragma unroll
    for (int off = 16; off >= 1; off >>= 1)
        sum += __shfl_xor_sync(0xffffffffu, sum, off);
    float qs = (float)km[q];                     // qscale = syb_mask[b,q]
    float inv = qs / sum;
#pragma unroll
    for (int j = 0; j < 8; j++)
        row[lane + j * 32] = v[j] * inv;
}

// ---------------- O = A @ V per (b,h) ----------------
// grid (4, B*H), block 256. Each block: 64 q-rows x 64 head-dims, K-loop over 256.
__global__ void __launch_bounds__(256) attn_av() {
    const int bh = blockIdx.y;
    const int b  = bh >> 4, h = bh & 15;
    const int q0 = blockIdx.x * 64;
    __shared__ float sA[64][33];
    __shared__ float sV[32][64];
    const float* Ap = g_s + ((size_t)bh * TTOK + q0) * TTOK;
    const float* Vp = g_v + (size_t)b * TTOK * DD + h * DH;
    const int tid = threadIdx.x, tr = tid >> 4, tc = tid & 15;
    float acc[4][4] = {};
    for (int k0 = 0; k0 < TTOK; k0 += 32) {
#pragma unroll
        for (int i = 0; i < 8; i++) {
            int e = tid + i * 256;               // 2048
            int r = e >> 5, c = e & 31;
            sA[r][c] = Ap[(size_t)r * TTOK + k0 + c];
            int r2 = e >> 6, c2 = e & 63;
            sV[r2][c2] = Vp[(size_t)(k0 + r2) * DD + c2];
        }
        __syncthreads();
#pragma unroll
        for (int kk = 0; kk < 32; kk++) {
            float ra[4], rv[4];
#pragma unroll
            for (int i = 0; i < 4; i++) ra[i] = sA[tr * 4 + i][kk];
            *(float4*)rv = *(float4*)&sV[kk][tc * 4];
#pragma unroll
            for (int i = 0; i < 4; i++)
#pragma unroll
                for (int j = 0; j < 4; j++)
                    acc[i][j] = fmaf(ra[i], rv[j], acc[i][j]);
        }
        __syncthreads();
    }
    float* Op = g_o + ((size_t)(b * TTOK + q0)) * DD + h * DH;
#pragma unroll
    for (int i = 0; i < 4; i++)
        *(float4*)&Op[(size_t)(tr * 4 + i) * DD + tc * 4] = *(float4*)&acc[i][0];
}

// ---------------- residual + layernorm: g_x = LN(g_x + addsrc) ----------------
__global__ void __launch_bounds__(256) ln_res(const float* __restrict__ addsrc,
                                              const float* __restrict__ gam,
                                              const float* __restrict__ bet) {
    const int row = blockIdx.x;
    const int tid = threadIdx.x;
    const int warp = tid >> 5, lane = tid & 31;
    float* xr = g_x + (size_t)row * DD;
    const float* ar = addsrc + (size_t)row * DD;
    __shared__ float red[8];

    float vals[4];
    float s = 0.f;
#pragma unroll
    for (int j = 0; j < 4; j++) {
        int c = tid + j * 256;
        vals[j] = xr[c] + ar[c];
        s += vals[j];
    }
#pragma unroll
    for (int off = 16; off >= 1; off >>= 1) s += __shfl_xor_sync(0xffffffffu, s, off);
    if (lane == 0) red[warp] = s;
    __syncthreads();
    float tot = 0.f;
#pragma unroll
    for (int w = 0; w < 8; w++) tot += red[w];
    const float mean = tot * (1.f / 1024.f);
    __syncthreads();

    float vs = 0.f;
#pragma unroll
    for (int j = 0; j < 4; j++) {
        float d = vals[j] - mean;
        vs += d * d;
    }
#pragma unroll
    for (int off = 16; off >= 1; off >>= 1) vs += __shfl_xor_sync(0xffffffffu, vs, off);
    if (lane == 0) red[warp] = vs;
    __syncthreads();
    float tot2 = 0.f;
#pragma unroll
    for (int w = 0; w < 8; w++) tot2 += red[w];
    const float var = tot2 * (1.f / 1024.f);
    const float rstd = rsqrtf(var + 1e-8f);

#pragma unroll
    for (int j = 0; j < 4; j++) {
        int c = tid + j * 256;
        xr[c] = (vals[j] - mean) * rstd * gam[c] + bet[c];
    }
}

// ---------------- host orchestration ----------------
extern "C" void kernel_launch(void* const* d_in, const int* in_sizes, int n_in,
                              void* d_out, int out_size) {
    const int*   ids   = (const int*)d_in[0];
    const int*   smask = (const int*)d_in[1];
    const int*   graph = (const int*)d_in[2];
    const float* emb   = (const float*)d_in[3];
    const float* w1    = (const float*)d_in[4];
    const float* b1    = (const float*)d_in[5];
    const float* w2    = (const float*)d_in[6];
    const float* b2    = (const float*)d_in[7];
    const float* pos   = (const float*)d_in[8];
    const float* wq    = (const float*)d_in[9];
    const float* bq    = (const float*)d_in[10];
    const float* wk    = (const float*)d_in[11];
    const float* bk    = (const float*)d_in[12];
    const float* wv    = (const float*)d_in[13];
    const float* bv    = (const float*)d_in[14];
    const float* ln1g  = (const float*)d_in[15];
    const float* ln1b  = (const float*)d_in[16];
    const float* fw1   = (const float*)d_in[17];
    const float* fb1   = (const float*)d_in[18];
    const float* fw2   = (const float*)d_in[19];
    const float* fb2   = (const float*)d_in[20];
    const float* ln2g  = (const float*)d_in[21];
    const float* ln2b  = (const float*)d_in[22];

    float *xe, *h1, *x, *q, *k, *v, *o, *ff;
    cudaGetSymbolAddress((void**)&xe, g_xe);
    cudaGetSymbolAddress((void**)&h1, g_h1);
    cudaGetSymbolAddress((void**)&x,  g_x);
    cudaGetSymbolAddress((void**)&q,  g_q);
    cudaGetSymbolAddress((void**)&k,  g_k);
    cudaGetSymbolAddress((void**)&v,  g_v);
    cudaGetSymbolAddress((void**)&o,  g_o);
    cudaGetSymbolAddress((void**)&ff, g_ff);

    // embedding + MLP + pos
    embed_gather<<<(NTOK * GDIM + 255) / 256, 256>>>(ids, emb);
    sgemm<true ><<<dim3(MLPH / 128, NTOK / 128), 256>>>(xe, w1, b1, h1, NTOK, MLPH, GDIM);
    sgemm<false><<<dim3(DD   / 128, NTOK / 128), 256>>>(h1, w2, b2, x,  NTOK, DD,   MLPH);
    add_pos<<<(NTOK * DD) / 256, 256>>>(pos);

    for (int i = 0; i < NBLK; i++) {
        const size_t wo = (size_t)i * DD * DD;
        sgemm<true><<<dim3(DD / 128, NTOK / 128), 256>>>(x, wq + wo, bq + i * DD, q, NTOK, DD, DD);
        sgemm<true><<<dim3(DD / 128, NTOK / 128), 256>>>(x, wk + wo, bk + i * DD, k, NTOK, DD, DD);
        sgemm<true><<<dim3(DD / 128, NTOK / 128), 256>>>(x, wv + wo, bv + i * DD, v, NTOK, DD, DD);

        attn_scores<<<dim3(4, 4, BB * HH), 256>>>();
        softmax_kernel<<<(BB * HH * TTOK) / 8, 256>>>(smask, graph);
        attn_av<<<dim3(4, BB * HH), 256>>>();
        ln_res<<<NTOK, 256>>>(o, ln1g + i * DD, ln1b + i * DD);

        sgemm<true ><<<dim3(FFH / 128, NTOK / 128), 256>>>(x, fw1 + (size_t)i * DD * FFH, fb1 + i * FFH, ff, NTOK, FFH, DD);
        sgemm<false><<<dim3(DD  / 128, NTOK / 128), 256>>>(ff, fw2 + (size_t)i * FFH * DD, fb2 + i * DD,  o,  NTOK, DD,  FFH);
        ln_res<<<NTOK, 256>>>(o, ln2g + i * DD, ln2b + i * DD);
    }

    cudaMemcpyAsync(d_out, x, sizeof(float) * NTOK * DD, cudaMemcpyDeviceToDevice);
}

// round 2
// speedup vs baseline: 2.6590x; 2.6590x over previous
#include <cuda_runtime.h>
#include <cuda_bf16.h>
#include <cstdint>

#define BB 16
#define TTOK 256
#define DD 1024
#define HH 16
#define NBLK 6
#define GDIM 300
#define MLPH 2048
#define FFH 4096
#define DH 64
#define NTOK (BB*TTOK)   // 4096

// ---------------- scratch (device globals; no allocation allowed) ----------------
__device__ float g_xe[NTOK*GDIM];
__device__ float g_h1[NTOK*MLPH];
__device__ float g_x [NTOK*DD];
__device__ float g_q [NTOK*DD];
__device__ float g_k [NTOK*DD];
__device__ float g_v [NTOK*DD];
__device__ float g_o [NTOK*DD];
__device__ float g_s [(size_t)BB*HH*TTOK*TTOK];
__device__ float g_ff[(size_t)NTOK*FFH];

// ---------------- embedding gather ----------------
__global__ void embed_gather(const int* __restrict__ ids, const float* __restrict__ emb) {
    int idx = blockIdx.x * blockDim.x + threadIdx.x;
    if (idx >= NTOK * GDIM) return;
    int bt = idx / GDIM;
    int c  = idx - bt * GDIM;
    g_xe[idx] = emb[(long long)ids[bt] * GDIM + c];
}

// ---------------- positional add ----------------
__global__ void add_pos(const float* __restrict__ pos) {
    int idx = blockIdx.x * blockDim.x + threadIdx.x;
    if (idx >= NTOK * DD) return;
    g_x[idx] += pos[idx % (TTOK * DD)];
}

// ---------------- split-bf16 helpers ----------------
// hi = truncation of fp32 to bf16 (exact bits), lo = rn(residual). hi+lo ~ 17-bit accurate.
__device__ __forceinline__ uint32_t pack_hi(float a, float b) {
    // result low 16 = hi(a), high 16 = hi(b)
    return __byte_perm(__float_as_uint(a), __float_as_uint(b), 0x7632);
}
__device__ __forceinline__ uint32_t pack_lo(float a, float b) {
    float ra = a - __uint_as_float(__float_as_uint(a) & 0xffff0000u);
    float rb = b - __uint_as_float(__float_as_uint(b) & 0xffff0000u);
    __nv_bfloat162 t = __floats2bfloat162_rn(ra, rb);
    return *reinterpret_cast<uint32_t*>(&t);
}

#define MMA_BF16(d, a, b)                                                        \
    asm volatile("mma.sync.aligned.m16n8k16.row.col.f32.bf16.bf16.f32 "          \
                 "{%0,%1,%2,%3},{%4,%5,%6,%7},{%8,%9},{%0,%1,%2,%3};"            \
                 : "+f"(d[0]), "+f"(d[1]), "+f"(d[2]), "+f"(d[3])                 \
                 : "r"(a[0]), "r"(a[1]), "r"(a[2]), "r"(a[3]), "r"(b[0]), "r"(b[1]))

// ---------------- split-bf16 GEMM: C = [relu](A @ W + bias) ----------------
// A: M x K fp32 row-major, W: K x N fp32 row-major, bias: N.
// M, N multiples of 128; K multiple of 4.
// Tile 128x128x32, 256 threads (8 warps of 64x32), 3-term bf16 split in fp32 accum.
template<bool RELU>
__global__ void __launch_bounds__(256, 1) bgemm(const float* __restrict__ A,
                                                const float* __restrict__ W,
                                                const float* __restrict__ bias,
                                                float* __restrict__ C,
                                                int M, int N, int K) {
    __shared__ __nv_bfloat16 sAh[128][40];   // [m][k], stride 40 bf16 (conflict-free)
    __shared__ __nv_bfloat16 sAl[128][40];
    __shared__ uint32_t      sWh[16][136];   // [k/2][n], each elem = bf16x2 (k,k+1)
    __shared__ uint32_t      sWl[16][136];

    const int tid   = threadIdx.x;
    const int lane  = tid & 31, warp = tid >> 5;
    const int wm    = (warp >> 2) * 64;      // warp m offset (0/64)
    const int wn    = (warp & 3) * 32;       // warp n offset (0/32/64/96)
    const int group = lane >> 2, quad = lane & 3;
    const int row0  = blockIdx.y * 128;
    const int col0  = blockIdx.x * 128;

    float acc[4][4][4];
#pragma unroll
    for (int i = 0; i < 4; i++)
#pragma unroll
        for (int j = 0; j < 4; j++)
#pragma unroll
            for (int e = 0; e < 4; e++) acc[i][j][e] = 0.f;

    float4 pa[4];
    float4 pw[2][2];

    auto ldg = [&](int k0) {
#pragma unroll
        for (int i = 0; i < 4; i++) {
            int idx = tid + i * 256;
            int ar  = idx >> 3;
            int kk  = k0 + (idx & 7) * 4;
            pa[i] = (kk < K) ? *(const float4*)(A + (size_t)(row0 + ar) * K + kk)
                             : make_float4(0.f, 0.f, 0.f, 0.f);
        }
#pragma unroll
        for (int i = 0; i < 2; i++) {
            int idx = tid + i * 256;
            int k2  = idx >> 5;
            int wc  = (idx & 31) * 4;
            int kr  = k0 + k2 * 2;
            pw[i][0] = (kr     < K) ? *(const float4*)(W + (size_t)kr       * N + col0 + wc)
                                    : make_float4(0.f, 0.f, 0.f, 0.f);
            pw[i][1] = (kr + 1 < K) ? *(const float4*)(W + (size_t)(kr + 1) * N + col0 + wc)
                                    : make_float4(0.f, 0.f, 0.f, 0.f);
        }
    };

    const int iters = (K + 31) >> 5;
    ldg(0);

    for (int it = 0; it < iters; ++it) {
        // ---- store staged tile to smem (convert fp32 -> bf16 hi/lo) ----
#pragma unroll
        for (int i = 0; i < 4; i++) {
            int idx = tid + i * 256;
            int ar  = idx >> 3;
            int ac  = (idx & 7) * 4;
            uint2 h, l;
            h.x = pack_hi(pa[i].x, pa[i].y); h.y = pack_hi(pa[i].z, pa[i].w);
            l.x = pack_lo(pa[i].x, pa[i].y); l.y = pack_lo(pa[i].z, pa[i].w);
            *(uint2*)&sAh[ar][ac] = h;
            *(uint2*)&sAl[ar][ac] = l;
        }
#pragma unroll
        for (int i = 0; i < 2; i++) {
            int idx = tid + i * 256;
            int k2  = idx >> 5;
            int wc  = (idx & 31) * 4;
            uint4 h, l;
            h.x = pack_hi(pw[i][0].x, pw[i][1].x);
            h.y = pack_hi(pw[i][0].y, pw[i][1].y);
            h.z = pack_hi(pw[i][0].z, pw[i][1].z);
            h.w = pack_hi(pw[i][0].w, pw[i][1].w);
            l.x = pack_lo(pw[i][0].x, pw[i][1].x);
            l.y = pack_lo(pw[i][0].y, pw[i][1].y);
            l.z = pack_lo(pw[i][0].z, pw[i][1].z);
            l.w = pack_lo(pw[i][0].w, pw[i][1].w);
            *(uint4*)&sWh[k2][wc] = h;
            *(uint4*)&sWl[k2][wc] = l;
        }
        __syncthreads();

        if (it + 1 < iters) ldg((it + 1) * 32);   // prefetch next tile during compute

        // ---- compute: 2 k-steps of m16n8k16, 3 split terms ----
#pragma unroll
        for (int ks = 0; ks < 2; ks++) {
            uint32_t bh[4][2], bl[4][2];
#pragma unroll
            for (int nt = 0; nt < 4; nt++) {
                int nc = wn + nt * 8 + group;
                bh[nt][0] = sWh[ks * 8 + quad][nc];
                bh[nt][1] = sWh[ks * 8 + quad + 4][nc];
                bl[nt][0] = sWl[ks * 8 + quad][nc];
                bl[nt][1] = sWl[ks * 8 + quad + 4][nc];
            }
#pragma unroll
            for (int mt = 0; mt < 4; mt++) {
                int r  = wm + mt * 16 + group;
                int kc = ks * 16 + quad * 2;
                uint32_t ah[4], al[4];
                ah[0] = *(uint32_t*)&sAh[r][kc];
                ah[1] = *(uint32_t*)&sAh[r + 8][kc];
                ah[2] = *(uint32_t*)&sAh[r][kc + 8];
                ah[3] = *(uint32_t*)&sAh[r + 8][kc + 8];
                al[0] = *(uint32_t*)&sAl[r][kc];
                al[1] = *(uint32_t*)&sAl[r + 8][kc];
                al[2] = *(uint32_t*)&sAl[r][kc + 8];
                al[3] = *(uint32_t*)&sAl[r + 8][kc + 8];
#pragma unroll
                for (int nt = 0; nt < 4; nt++) MMA_BF16(acc[mt][nt], ah, bh[nt]);
#pragma unroll
                for (int nt = 0; nt < 4; nt++) MMA_BF16(acc[mt][nt], al, bh[nt]);
#pragma unroll
                for (int nt = 0; nt < 4; nt++) MMA_BF16(acc[mt][nt], ah, bl[nt]);
            }
        }
        __syncthreads();
    }

    // ---- epilogue: bias (+ relu) + store ----
#pragma unroll
    for (int mt = 0; mt < 4; mt++) {
        int r = row0 + wm + mt * 16 + group;
#pragma unroll
        for (int nt = 0; nt < 4; nt++) {
            int c  = col0 + wn + nt * 8 + quad * 2;
            float b0 = bias[c], b1 = bias[c + 1];
            float v0 = acc[mt][nt][0] + b0;
            float v1 = acc[mt][nt][1] + b1;
            float v2 = acc[mt][nt][2] + b0;
            float v3 = acc[mt][nt][3] + b1;
            if (RELU) {
                v0 = fmaxf(v0, 0.f); v1 = fmaxf(v1, 0.f);
                v2 = fmaxf(v2, 0.f); v3 = fmaxf(v3, 0.f);
            }
            float2 o0 = make_float2(v0, v1);
            float2 o1 = make_float2(v2, v3);
            *(float2*)&C[(size_t)r * N + c]       = o0;
            *(float2*)&C[(size_t)(r + 8) * N + c] = o1;
        }
    }
}

// ---------------- attention scores: S[b,h,q,k] = Q_row . K_row ----------------
__global__ void __launch_bounds__(256) attn_scores() {
    const int bh = blockIdx.z;
    const int b  = bh >> 4, h = bh & 15;
    const int q0 = blockIdx.y * 64, n0 = blockIdx.x * 64;
    __shared__ float sQ[64][65];
    __shared__ float sK[64][65];
    const int tid = threadIdx.x;
    const float* Qp = g_q + (size_t)b * TTOK * DD + h * DH;
    const float* Kp = g_k + (size_t)b * TTOK * DD + h * DH;
#pragma unroll
    for (int i = 0; i < 16; i++) {
        int e = tid + i * 256;
        int r = e >> 6, c = e & 63;
        sQ[r][c] = Qp[(size_t)(q0 + r) * DD + c];
        sK[r][c] = Kp[(size_t)(n0 + r) * DD + c];
    }
    __syncthreads();
    const int tr = tid >> 4, tc = tid & 15;
    float acc[4][4] = {};
#pragma unroll 8
    for (int kk = 0; kk < 64; kk++) {
        float rq[4], rk[4];
#pragma unroll
        for (int i = 0; i < 4; i++) rq[i] = sQ[tr * 4 + i][kk];
#pragma unroll
        for (int j = 0; j < 4; j++) rk[j] = sK[tc * 4 + j][kk];
#pragma unroll
        for (int i = 0; i < 4; i++)
#pragma unroll
            for (int j = 0; j < 4; j++)
                acc[i][j] = fmaf(rq[i], rk[j], acc[i][j]);
    }
    float* Sp = g_s + ((size_t)bh * TTOK + q0) * TTOK + n0;
#pragma unroll
    for (int i = 0; i < 4; i++)
        *(float4*)&Sp[(size_t)(tr * 4 + i) * TTOK + tc * 4] = *(float4*)&acc[i][0];
}

// ---------------- masked softmax, in place on g_s ----------------
__global__ void __launch_bounds__(256) softmax_kernel(const int* __restrict__ smask,
                                                      const int* __restrict__ graph) {
    const int warp = threadIdx.x >> 5, lane = threadIdx.x & 31;
    const int r = blockIdx.x * 8 + warp;
    const int b = r >> 12;
    const int q = r & (TTOK - 1);
    float* row = g_s + (size_t)r * TTOK;
    const int* km = smask + b * TTOK;
    const int* gm = graph + ((size_t)b * TTOK + q) * TTOK;
    const float NEGF = -4294967295.0f;

    float v[8];
    float m = -3.4e38f;
#pragma unroll
    for (int j = 0; j < 8; j++) {
        int c = lane + j * 32;
        float s = row[c] * 0.125f;
        if (!(km[c] > 0 && gm[c] > 0)) s = NEGF;
        v[j] = s;
        m = fmaxf(m, s);
    }
#pragma unroll
    for (int off = 16; off >= 1; off >>= 1)
        m = fmaxf(m, __shfl_xor_sync(0xffffffffu, m, off));
    float sum = 0.f;
#pragma unroll
    for (int j = 0; j < 8; j++) {
        v[j] = expf(v[j] - m);
        sum += v[j];
    }
#pragma unroll
    for (int off = 16; off >= 1; off >>= 1)
        sum += __shfl_xor_sync(0xffffffffu, sum, off);
    float qs = (float)km[q];
    float inv = qs / sum;
#pragma unroll
    for (int j = 0; j < 8; j++)
        row[lane + j * 32] = v[j] * inv;
}

// ---------------- O = A @ V per (b,h) ----------------
__global__ void __launch_bounds__(256) attn_av() {
    const int bh = blockIdx.y;
    const int b  = bh >> 4, h = bh & 15;
    const int q0 = blockIdx.x * 64;
    __shared__ float sA[64][33];
    __shared__ float sV[32][64];
    const float* Ap = g_s + ((size_t)bh * TTOK + q0) * TTOK;
    const float* Vp = g_v + (size_t)b * TTOK * DD + h * DH;
    const int tid = threadIdx.x, tr = tid >> 4, tc = tid & 15;
    float acc[4][4] = {};
    for (int k0 = 0; k0 < TTOK; k0 += 32) {
#pragma unroll
        for (int i = 0; i < 8; i++) {
            int e = tid + i * 256;
            int r = e >> 5, c = e & 31;
            sA[r][c] = Ap[(size_t)r * TTOK + k0 + c];
            int r2 = e >> 6, c2 = e & 63;
            sV[r2][c2] = Vp[(size_t)(k0 + r2) * DD + c2];
        }
        __syncthreads();
#pragma unroll
        for (int kk = 0; kk < 32; kk++) {
            float ra[4], rv[4];
#pragma unroll
            for (int i = 0; i < 4; i++) ra[i] = sA[tr * 4 + i][kk];
            *(float4*)rv = *(float4*)&sV[kk][tc * 4];
#pragma unroll
            for (int i = 0; i < 4; i++)
#pragma unroll
                for (int j = 0; j < 4; j++)
                    acc[i][j] = fmaf(ra[i], rv[j], acc[i][j]);
        }
        __syncthreads();
    }
    float* Op = g_o + ((size_t)(b * TTOK + q0)) * DD + h * DH;
#pragma unroll
    for (int i = 0; i < 4; i++)
        *(float4*)&Op[(size_t)(tr * 4 + i) * DD + tc * 4] = *(float4*)&acc[i][0];
}

// ---------------- residual + layernorm: g_x = LN(g_x + addsrc) ----------------
__global__ void __launch_bounds__(256) ln_res(const float* __restrict__ addsrc,
                                              const float* __restrict__ gam,
                                              const float* __restrict__ bet) {
    const int row = blockIdx.x;
    const int tid = threadIdx.x;
    const int warp = tid >> 5, lane = tid & 31;
    float* xr = g_x + (size_t)row * DD;
    const float* ar = addsrc + (size_t)row * DD;
    __shared__ float red[8];

    float vals[4];
    float s = 0.f;
#pragma unroll
    for (int j = 0; j < 4; j++) {
        int c = tid + j * 256;
        vals[j] = xr[c] + ar[c];
        s += vals[j];
    }
#pragma unroll
    for (int off = 16; off >= 1; off >>= 1) s += __shfl_xor_sync(0xffffffffu, s, off);
    if (lane == 0) red[warp] = s;
    __syncthreads();
    float tot = 0.f;
#pragma unroll
    for (int w = 0; w < 8; w++) tot += red[w];
    const float mean = tot * (1.f / 1024.f);
    __syncthreads();

    float vs = 0.f;
#pragma unroll
    for (int j = 0; j < 4; j++) {
        float d = vals[j] - mean;
        vs += d * d;
    }
#pragma unroll
    for (int off = 16; off >= 1; off >>= 1) vs += __shfl_xor_sync(0xffffffffu, vs, off);
    if (lane == 0) red[warp] = vs;
    __syncthreads();
    float tot2 = 0.f;
#pragma unroll
    for (int w = 0; w < 8; w++) tot2 += red[w];
    const float var = tot2 * (1.f / 1024.f);
    const float rstd = rsqrtf(var + 1e-8f);

#pragma unroll
    for (int j = 0; j < 4; j++) {
        int c = tid + j * 256;
        xr[c] = (vals[j] - mean) * rstd * gam[c] + bet[c];
    }
}

// ---------------- host orchestration ----------------
extern "C" void kernel_launch(void* const* d_in, const int* in_sizes, int n_in,
                              void* d_out, int out_size) {
    const int*   ids   = (const int*)d_in[0];
    const int*   smask = (const int*)d_in[1];
    const int*   graph = (const int*)d_in[2];
    const float* emb   = (const float*)d_in[3];
    const float* w1    = (const float*)d_in[4];
    const float* b1    = (const float*)d_in[5];
    const float* w2    = (const float*)d_in[6];
    const float* b2    = (const float*)d_in[7];
    const float* pos   = (const float*)d_in[8];
    const float* wq    = (const float*)d_in[9];
    const float* bq    = (const float*)d_in[10];
    const float* wk    = (const float*)d_in[11];
    const float* bk    = (const float*)d_in[12];
    const float* wv    = (const float*)d_in[13];
    const float* bv    = (const float*)d_in[14];
    const float* ln1g  = (const float*)d_in[15];
    const float* ln1b  = (const float*)d_in[16];
    const float* fw1   = (const float*)d_in[17];
    const float* fb1   = (const float*)d_in[18];
    const float* fw2   = (const float*)d_in[19];
    const float* fb2   = (const float*)d_in[20];
    const float* ln2g  = (const float*)d_in[21];
    const float* ln2b  = (const float*)d_in[22];

    float *xe, *h1, *x, *q, *k, *v, *o, *ff;
    cudaGetSymbolAddress((void**)&xe, g_xe);
    cudaGetSymbolAddress((void**)&h1, g_h1);
    cudaGetSymbolAddress((void**)&x,  g_x);
    cudaGetSymbolAddress((void**)&q,  g_q);
    cudaGetSymbolAddress((void**)&k,  g_k);
    cudaGetSymbolAddress((void**)&v,  g_v);
    cudaGetSymbolAddress((void**)&o,  g_o);
    cudaGetSymbolAddress((void**)&ff, g_ff);

    // embedding + MLP + pos
    embed_gather<<<(NTOK * GDIM + 255) / 256, 256>>>(ids, emb);
    bgemm<true ><<<dim3(MLPH / 128, NTOK / 128), 256>>>(xe, w1, b1, h1, NTOK, MLPH, GDIM);
    bgemm<false><<<dim3(DD   / 128, NTOK / 128), 256>>>(h1, w2, b2, x,  NTOK, DD,   MLPH);
    add_pos<<<(NTOK * DD) / 256, 256>>>(pos);

    for (int i = 0; i < NBLK; i++) {
        const size_t wo = (size_t)i * DD * DD;
        bgemm<true><<<dim3(DD / 128, NTOK / 128), 256>>>(x, wq + wo, bq + i * DD, q, NTOK, DD, DD);
        bgemm<true><<<dim3(DD / 128, NTOK / 128), 256>>>(x, wk + wo, bk + i * DD, k, NTOK, DD, DD);
        bgemm<true><<<dim3(DD / 128, NTOK / 128), 256>>>(x, wv + wo, bv + i * DD, v, NTOK, DD, DD);

        attn_scores<<<dim3(4, 4, BB * HH), 256>>>();
        softmax_kernel<<<(BB * HH * TTOK) / 8, 256>>>(smask, graph);
        attn_av<<<dim3(4, BB * HH), 256>>>();
        ln_res<<<NTOK, 256>>>(o, ln1g + i * DD, ln1b + i * DD);

        bgemm<true ><<<dim3(FFH / 128, NTOK / 128), 256>>>(x, fw1 + (size_t)i * DD * FFH, fb1 + i * FFH, ff, NTOK, FFH, DD);
        bgemm<false><<<dim3(DD  / 128, NTOK / 128), 256>>>(ff, fw2 + (size_t)i * FFH * DD, fb2 + i * DD,  o,  NTOK, DD,  FFH);
        ln_res<<<NTOK, 256>>>(o, ln2g + i * DD, ln2b + i * DD);
    }

    cudaMemcpyAsync(d_out, x, sizeof(float) * NTOK * DD, cudaMemcpyDeviceToDevice);
}

// round 4
// speedup vs baseline: 2.9098x; 1.0943x over previous
#include <cuda_runtime.h>
#include <cuda_bf16.h>
#include <cstdint>

#define BB 16
#define TTOK 256
#define DD 1024
#define HH 16
#define NBLK 6
#define GDIM 300
#define GPAD 320
#define MLPH 2048
#define FFH 4096
#define DH 64
#define NTOK (BB*TTOK)   // 4096

// ---------------- scratch (device globals; no allocation allowed) ----------------
__device__ float g_xe[NTOK*GDIM];
__device__ float g_x [NTOK*DD];
__device__ float g_q [NTOK*DD];
__device__ float g_k [NTOK*DD];
__device__ float g_v [NTOK*DD];
__device__ float g_o [NTOK*DD];
__device__ float g_s [(size_t)BB*HH*TTOK*TTOK];

// split-bf16 activations (hi/lo)
__device__ uint16_t g_xeh[NTOK*GPAD],  g_xel[NTOK*GPAD];
__device__ uint16_t g_xh [NTOK*DD],    g_xl [NTOK*DD];
__device__ uint16_t g_h1h[NTOK*MLPH],  g_h1l[NTOK*MLPH];
__device__ uint16_t g_ffh[(size_t)NTOK*FFH], g_ffl[(size_t)NTOK*FFH];

// packed split-bf16 weights: [K/2][N] uint32 (bf16x2 of k,k+1)
#define OFF_MLP1 0ull
#define OFF_MLP2 327680ull                         // 160*2048
#define OFF_QKV  1376256ull                        // + 1024*1024
#define QKV_BLK  1572864ull                        // 3*512*1024
#define QKV_MAT  524288ull
#define OFF_FF1  10813440ull                       // OFF_QKV + 6*QKV_BLK
#define FF1_BLK  2097152ull                        // 512*4096
#define OFF_FF2  23396352ull                       // OFF_FF1 + 6*FF1_BLK
#define FF2_BLK  2097152ull                        // 2048*1024
#define W_TOTAL  35979264ull
__device__ uint32_t g_wh[W_TOTAL];
__device__ uint32_t g_wl[W_TOTAL];

// ---------------- split helpers ----------------
__device__ __forceinline__ uint32_t pack_hi(float a, float b) {
    return __byte_perm(__float_as_uint(a), __float_as_uint(b), 0x7632);
}
__device__ __forceinline__ uint32_t pack_lo(float a, float b) {
    float ra = a - __uint_as_float(__float_as_uint(a) & 0xffff0000u);
    float rb = b - __uint_as_float(__float_as_uint(b) & 0xffff0000u);
    __nv_bfloat162 t = __floats2bfloat162_rn(ra, rb);
    return *reinterpret_cast<uint32_t*>(&t);
}
__device__ __forceinline__ uint16_t hi16(float v) {
    return (uint16_t)(__float_as_uint(v) >> 16);
}
__device__ __forceinline__ uint16_t lo16(float v) {
    float r = v - __uint_as_float(__float_as_uint(v) & 0xffff0000u);
    __nv_bfloat16 b = __float2bfloat16(r);
    return *reinterpret_cast<uint16_t*>(&b);
}

// ---------------- weight packing: W[K][N] fp32 -> [Kpad/2][N] hi/lo bf16x2 ----------------
__global__ void pack_w(const float* __restrict__ W, uint32_t* __restrict__ oh,
                       uint32_t* __restrict__ ol, int K, int N) {
    int n  = blockIdx.x * 256 + threadIdx.x;
    int k2 = blockIdx.y;
    float a = (2 * k2     < K) ? W[(size_t)(2 * k2)     * N + n] : 0.f;
    float b = (2 * k2 + 1 < K) ? W[(size_t)(2 * k2 + 1) * N + n] : 0.f;
    oh[(size_t)k2 * N + n] = pack_hi(a, b);
    ol[(size_t)k2 * N + n] = pack_lo(a, b);
}

// ---------------- embedding gather + split-convert ----------------
__global__ void embed_gather(const int* __restrict__ ids, const float* __restrict__ emb) {
    int idx = blockIdx.x * blockDim.x + threadIdx.x;
    if (idx >= NTOK * GDIM) return;
    int bt = idx / GDIM;
    int c  = idx - bt * GDIM;
    g_xe[idx] = emb[(long long)ids[bt] * GDIM + c];
}
__global__ void conv_xe() {
    int idx = blockIdx.x * 256 + threadIdx.x;
    if (idx >= NTOK * GPAD) return;
    int m = idx / GPAD, k = idx - m * GPAD;
    float v = (k < GDIM) ? g_xe[m * GDIM + k] : 0.f;
    g_xeh[idx] = hi16(v);
    g_xel[idx] = lo16(v);
}

// ---------------- positional add (+ split write) ----------------
__global__ void add_pos(const float* __restrict__ pos) {
    int idx = blockIdx.x * blockDim.x + threadIdx.x;
    if (idx >= NTOK * DD) return;
    float v = g_x[idx] + pos[idx % (TTOK * DD)];
    g_x[idx] = v;
    g_xh[idx] = hi16(v);
    g_xl[idx] = lo16(v);
}

// ---------------- cp.async helpers ----------------
__device__ __forceinline__ uint32_t smem_u32(const void* p) {
    uint32_t a;
    asm("{ .reg .u64 t; cvta.to.shared.u64 t, %1; cvt.u32.u64 %0, t; }" : "=r"(a) : "l"(p));
    return a;
}
__device__ __forceinline__ void cp16(uint32_t saddr, const void* g) {
    asm volatile("cp.async.cg.shared.global [%0], [%1], 16;" :: "r"(saddr), "l"(g));
}
__device__ __forceinline__ void cp_commit() {
    asm volatile("cp.async.commit_group;" ::: "memory");
}
template<int N>
__device__ __forceinline__ void cp_wait() {
    asm volatile("cp.async.wait_group %0;" :: "n"(N) : "memory");
}

#define MMA_BF16(d, a, b)                                                        \
    asm volatile("mma.sync.aligned.m16n8k16.row.col.f32.bf16.bf16.f32 "          \
                 "{%0,%1,%2,%3},{%4,%5,%6,%7},{%8,%9},{%0,%1,%2,%3};"            \
                 : "+f"(d[0]), "+f"(d[1]), "+f"(d[2]), "+f"(d[3])                 \
                 : "r"(a[0]), "r"(a[1]), "r"(a[2]), "r"(a[3]), "r"(b[0]), "r"(b[1]))

// smem stage layout (bytes): Ah[128][40]bf16 @0 (10240) | Al @10240 | Wh[16][136]u32 @20480 (8704) | Wl @29184
#define STG_SZ 37888
#define GSMEM  (2*STG_SZ)

// ---------------- split-bf16 HGEMM (pre-split operands) ----------------
// C = [relu](A @ W + bias). A via (Ah,Al) bf16 [M][K]; W via packed (Wh,Wl) [K/2][N].
// MODE 0: write C fp32. MODE 1: write split bf16 (Ch,Cl). Tile 128x128x32, 256 thr, 2 CTA/SM.
template<int MODE, bool RELU>
__global__ void __launch_bounds__(256, 2)
hgemm(const uint16_t* __restrict__ Ah, const uint16_t* __restrict__ Al,
      const uint32_t* __restrict__ Wh, const uint32_t* __restrict__ Wl,
      const float* __restrict__ bias,
      float* __restrict__ C, uint16_t* __restrict__ Ch, uint16_t* __restrict__ Cl,
      int M, int N, int K) {
    extern __shared__ char smc[];
    const uint32_t smb = smem_u32(smc);
    const int tid  = threadIdx.x;
    const int lane = tid & 31, warp = tid >> 5;
    const int wm   = (warp >> 2) * 64;
    const int wn   = (warp & 3) * 32;
    const int group = lane >> 2, quad = lane & 3;
    const int row0 = blockIdx.y * 128;
    const int col0 = blockIdx.x * 128;

    float acc[4][4][4];
#pragma unroll
    for (int i = 0; i < 4; i++)
#pragma unroll
        for (int j = 0; j < 4; j++)
#pragma unroll
            for (int e = 0; e < 4; e++) acc[i][j][e] = 0.f;

    const int iters = K >> 5;

    auto fill = [&](int stage, int k0) {
        uint32_t sb = smb + stage * STG_SZ;
#pragma unroll
        for (int i = 0; i < 2; i++) {
            int c = tid + i * 256;
            int row = c >> 2, kc = c & 3;
            size_t g = (size_t)(row0 + row) * K + k0 + kc * 8;
            uint32_t so = sb + row * 80 + kc * 16;
            cp16(so, Ah + g);
            cp16(so + 10240, Al + g);
        }
        int k2b = k0 >> 1;
#pragma unroll
        for (int i = 0; i < 2; i++) {
            int c = tid + i * 256;
            int k2r = c >> 5, nch = c & 31;
            size_t g = (size_t)(k2b + k2r) * N + col0 + nch * 4;
            uint32_t so = sb + 20480 + k2r * 544 + nch * 16;
            cp16(so, Wh + g);
            cp16(so + 8704, Wl + g);
        }
    };

    auto compute = [&](int stage) {
        const uint16_t* sAh = (const uint16_t*)(smc + stage * STG_SZ);
        const uint16_t* sAl = (const uint16_t*)(smc + stage * STG_SZ + 10240);
        const uint32_t* sWh = (const uint32_t*)(smc + stage * STG_SZ + 20480);
        const uint32_t* sWl = (const uint32_t*)(smc + stage * STG_SZ + 29184);
#pragma unroll
        for (int ks = 0; ks < 2; ks++) {
            uint32_t bh[4][2], bl[4][2];
#pragma unroll
            for (int nt = 0; nt < 4; nt++) {
                int nc = wn + nt * 8 + group;
                bh[nt][0] = sWh[(ks * 8 + quad) * 136 + nc];
                bh[nt][1] = sWh[(ks * 8 + quad + 4) * 136 + nc];
                bl[nt][0] = sWl[(ks * 8 + quad) * 136 + nc];
                bl[nt][1] = sWl[(ks * 8 + quad + 4) * 136 + nc];
            }
#pragma unroll
            for (int mt = 0; mt < 4; mt++) {
                int r  = wm + mt * 16 + group;
                int kc = ks * 16 + quad * 2;
                uint32_t ah[4], al[4];
                ah[0] = *(const uint32_t*)&sAh[r * 40 + kc];
                ah[1] = *(const uint32_t*)&sAh[(r + 8) * 40 + kc];
                ah[2] = *(const uint32_t*)&sAh[r * 40 + kc + 8];
                ah[3] = *(const uint32_t*)&sAh[(r + 8) * 40 + kc + 8];
                al[0] = *(const uint32_t*)&sAl[r * 40 + kc];
                al[1] = *(const uint32_t*)&sAl[(r + 8) * 40 + kc];
                al[2] = *(const uint32_t*)&sAl[r * 40 + kc + 8];
                al[3] = *(const uint32_t*)&sAl[(r + 8) * 40 + kc + 8];
#pragma unroll
                for (int nt = 0; nt < 4; nt++) MMA_BF16(acc[mt][nt], ah, bh[nt]);
#pragma unroll
                for (int nt = 0; nt < 4; nt++) MMA_BF16(acc[mt][nt], al, bh[nt]);
#pragma unroll
                for (int nt = 0; nt < 4; nt++) MMA_BF16(acc[mt][nt], ah, bl[nt]);
            }
        }
    };

    fill(0, 0); cp_commit();
    if (iters > 1) { fill(1, 32); cp_commit(); }

    for (int it = 0; it < iters; ++it) {
        if (it + 1 < iters) cp_wait<1>(); else cp_wait<0>();
        __syncthreads();
        compute(it & 1);
        __syncthreads();
        if (it + 2 < iters) { fill(it & 1, (it + 2) * 32); cp_commit(); }
    }

    // ---- epilogue ----
#pragma unroll
    for (int mt = 0; mt < 4; mt++) {
        int r = row0 + wm + mt * 16 + group;
#pragma unroll
        for (int nt = 0; nt < 4; nt++) {
            int c  = col0 + wn + nt * 8 + quad * 2;
            float b0 = bias[c], b1 = bias[c + 1];
            float v0 = acc[mt][nt][0] + b0;
            float v1 = acc[mt][nt][1] + b1;
            float v2 = acc[mt][nt][2] + b0;
            float v3 = acc[mt][nt][3] + b1;
            if (RELU) {
                v0 = fmaxf(v0, 0.f); v1 = fmaxf(v1, 0.f);
                v2 = fmaxf(v2, 0.f); v3 = fmaxf(v3, 0.f);
            }
            if (MODE == 0) {
                *(float2*)&C[(size_t)r * N + c]       = make_float2(v0, v1);
                *(float2*)&C[(size_t)(r + 8) * N + c] = make_float2(v2, v3);
            } else {
                uint32_t* ChW = (uint32_t*)Ch;
                uint32_t* ClW = (uint32_t*)Cl;
                size_t i0 = ((size_t)r * N + c) >> 1;
                size_t i1 = ((size_t)(r + 8) * N + c) >> 1;
                ChW[i0] = pack_hi(v0, v1); ClW[i0] = pack_lo(v0, v1);
                ChW[i1] = pack_hi(v2, v3); ClW[i1] = pack_lo(v2, v3);
            }
        }
    }
}

// ---------------- attention scores ----------------
__global__ void __launch_bounds__(256) attn_scores() {
    const int bh = blockIdx.z;
    const int b  = bh >> 4, h = bh & 15;
    const int q0 = blockIdx.y * 64, n0 = blockIdx.x * 64;
    __shared__ float sQ[64][65];
    __shared__ float sK[64][65];
    const int tid = threadIdx.x;
    const float* Qp = g_q + (size_t)b * TTOK * DD + h * DH;
    const float* Kp = g_k + (size_t)b * TTOK * DD + h * DH;
#pragma unroll
    for (int i = 0; i < 16; i++) {
        int e = tid + i * 256;
        int r = e >> 6, c = e & 63;
        sQ[r][c] = Qp[(size_t)(q0 + r) * DD + c];
        sK[r][c] = Kp[(size_t)(n0 + r) * DD + c];
    }
    __syncthreads();
    const int tr = tid >> 4, tc = tid & 15;
    float acc[4][4] = {};
#pragma unroll 8
    for (int kk = 0; kk < 64; kk++) {
        float rq[4], rk[4];
#pragma unroll
        for (int i = 0; i < 4; i++) rq[i] = sQ[tr * 4 + i][kk];
#pragma unroll
        for (int j = 0; j < 4; j++) rk[j] = sK[tc * 4 + j][kk];
#pragma unroll
        for (int i = 0; i < 4; i++)
#pragma unroll
            for (int j = 0; j < 4; j++)
                acc[i][j] = fmaf(rq[i], rk[j], acc[i][j]);
    }
    float* Sp = g_s + ((size_t)bh * TTOK + q0) * TTOK + n0;
#pragma unroll
    for (int i = 0; i < 4; i++)
        *(float4*)&Sp[(size_t)(tr * 4 + i) * TTOK + tc * 4] = *(float4*)&acc[i][0];
}

// ---------------- masked softmax ----------------
__global__ void __launch_bounds__(256) softmax_kernel(const int* __restrict__ smask,
                                                      const int* __restrict__ graph) {
    const int warp = threadIdx.x >> 5, lane = threadIdx.x & 31;
    const int r = blockIdx.x * 8 + warp;
    const int b = r >> 12;
    const int q = r & (TTOK - 1);
    float* row = g_s + (size_t)r * TTOK;
    const int* km = smask + b * TTOK;
    const int* gm = graph + ((size_t)b * TTOK + q) * TTOK;
    const float NEGF = -4294967295.0f;

    float v[8];
    float m = -3.4e38f;
#pragma unroll
    for (int j = 0; j < 8; j++) {
        int c = lane + j * 32;
        float s = row[c] * 0.125f;
        if (!(km[c] > 0 && gm[c] > 0)) s = NEGF;
        v[j] = s;
        m = fmaxf(m, s);
    }
#pragma unroll
    for (int off = 16; off >= 1; off >>= 1)
        m = fmaxf(m, __shfl_xor_sync(0xffffffffu, m, off));
    float sum = 0.f;
#pragma unroll
    for (int j = 0; j < 8; j++) {
        v[j] = expf(v[j] - m);
        sum += v[j];
    }
#pragma unroll
    for (int off = 16; off >= 1; off >>= 1)
        sum += __shfl_xor_sync(0xffffffffu, sum, off);
    float qs = (float)km[q];
    float inv = qs / sum;
#pragma unroll
    for (int j = 0; j < 8; j++)
        row[lane + j * 32] = v[j] * inv;
}

// ---------------- O = A @ V ----------------
__global__ void __launch_bounds__(256) attn_av() {
    const int bh = blockIdx.y;
    const int b  = bh >> 4, h = bh & 15;
    const int q0 = blockIdx.x * 64;
    __shared__ float sA[64][33];
    __shared__ float sV[32][64];
    const float* Ap = g_s + ((size_t)bh * TTOK + q0) * TTOK;
    const float* Vp = g_v + (size_t)b * TTOK * DD + h * DH;
    const int tid = threadIdx.x, tr = tid >> 4, tc = tid & 15;
    float acc[4][4] = {};
    for (int k0 = 0; k0 < TTOK; k0 += 32) {
#pragma unroll
        for (int i = 0; i < 8; i++) {
            int e = tid + i * 256;
            int r = e >> 5, c = e & 31;
            sA[r][c] = Ap[(size_t)r * TTOK + k0 + c];
            int r2 = e >> 6, c2 = e & 63;
            sV[r2][c2] = Vp[(size_t)(k0 + r2) * DD + c2];
        }
        __syncthreads();
#pragma unroll
        for (int kk = 0; kk < 32; kk++) {
            float ra[4], rv[4];
#pragma unroll
            for (int i = 0; i < 4; i++) ra[i] = sA[tr * 4 + i][kk];
            *(float4*)rv = *(float4*)&sV[kk][tc * 4];
#pragma unroll
            for (int i = 0; i < 4; i++)
#pragma unroll
                for (int j = 0; j < 4; j++)
                    acc[i][j] = fmaf(ra[i], rv[j], acc[i][j]);
        }
        __syncthreads();
    }
    float* Op = g_o + ((size_t)(b * TTOK + q0)) * DD + h * DH;
#pragma unroll
    for (int i = 0; i < 4; i++)
        *(float4*)&Op[(size_t)(tr * 4 + i) * DD + tc * 4] = *(float4*)&acc[i][0];
}

// ---------------- residual + layernorm (+ split write) ----------------
__global__ void __launch_bounds__(256) ln_res(const float* __restrict__ addsrc,
                                              const float* __restrict__ gam,
                                              const float* __restrict__ bet) {
    const int row = blockIdx.x;
    const int tid = threadIdx.x;
    const int warp = tid >> 5, lane = tid & 31;
    float* xr = g_x + (size_t)row * DD;
    const float* ar = addsrc + (size_t)row * DD;
    __shared__ float red[8];

    float vals[4];
    float s = 0.f;
#pragma unroll
    for (int j = 0; j < 4; j++) {
        int c = tid + j * 256;
        vals[j] = xr[c] + ar[c];
        s += vals[j];
    }
#pragma unroll
    for (int off = 16; off >= 1; off >>= 1) s += __shfl_xor_sync(0xffffffffu, s, off);
    if (lane == 0) red[warp] = s;
    __syncthreads();
    float tot = 0.f;
#pragma unroll
    for (int w = 0; w < 8; w++) tot += red[w];
    const float mean = tot * (1.f / 1024.f);
    __syncthreads();

    float vs = 0.f;
#pragma unroll
    for (int j = 0; j < 4; j++) {
        float d = vals[j] - mean;
        vs += d * d;
    }
#pragma unroll
    for (int off = 16; off >= 1; off >>= 1) vs += __shfl_xor_sync(0xffffffffu, vs, off);
    if (lane == 0) red[warp] = vs;
    __syncthreads();
    float tot2 = 0.f;
#pragma unroll
    for (int w = 0; w < 8; w++) tot2 += red[w];
    const float var = tot2 * (1.f / 1024.f);
    const float rstd = rsqrtf(var + 1e-8f);

#pragma unroll
    for (int j = 0; j < 4; j++) {
        int c = tid + j * 256;
        float v = (vals[j] - mean) * rstd * gam[c] + bet[c];
        xr[c] = v;
        g_xh[(size_t)row * DD + c] = hi16(v);
        g_xl[(size_t)row * DD + c] = lo16(v);
    }
}

// ---------------- host orchestration ----------------
extern "C" void kernel_launch(void* const* d_in, const int* in_sizes, int n_in,
                              void* d_out, int out_size) {
    const int*   ids   = (const int*)d_in[0];
    const int*   smask = (const int*)d_in[1];
    const int*   graph = (const int*)d_in[2];
    const float* emb   = (const float*)d_in[3];
    const float* w1    = (const float*)d_in[4];
    const float* b1    = (const float*)d_in[5];
    const float* w2    = (const float*)d_in[6];
    const float* b2    = (const float*)d_in[7];
    const float* pos   = (const float*)d_in[8];
    const float* wq    = (const float*)d_in[9];
    const float* bq    = (const float*)d_in[10];
    const float* wk    = (const float*)d_in[11];
    const float* bk    = (const float*)d_in[12];
    const float* wv    = (const float*)d_in[13];
    const float* bv    = (const float*)d_in[14];
    const float* ln1g  = (const float*)d_in[15];
    const float* ln1b  = (const float*)d_in[16];
    const float* fw1   = (const float*)d_in[17];
    const float* fb1   = (const float*)d_in[18];
    const float* fw2   = (const float*)d_in[19];
    const float* fb2   = (const float*)d_in[20];
    const float* ln2g  = (const float*)d_in[21];
    const float* ln2b  = (const float*)d_in[22];

    float *x, *q, *k, *v, *o;
    uint16_t *xeh, *xel, *xh, *xl, *h1h, *h1l, *ffh, *ffl;
    uint32_t *wh, *wl;
    cudaGetSymbolAddress((void**)&x,   g_x);
    cudaGetSymbolAddress((void**)&q,   g_q);
    cudaGetSymbolAddress((void**)&k,   g_k);
    cudaGetSymbolAddress((void**)&v,   g_v);
    cudaGetSymbolAddress((void**)&o,   g_o);
    cudaGetSymbolAddress((void**)&xeh, g_xeh);
    cudaGetSymbolAddress((void**)&xel, g_xel);
    cudaGetSymbolAddress((void**)&xh,  g_xh);
    cudaGetSymbolAddress((void**)&xl,  g_xl);
    cudaGetSymbolAddress((void**)&h1h, g_h1h);
    cudaGetSymbolAddress((void**)&h1l, g_h1l);
    cudaGetSymbolAddress((void**)&ffh, g_ffh);
    cudaGetSymbolAddress((void**)&ffl, g_ffl);
    cudaGetSymbolAddress((void**)&wh,  g_wh);
    cudaGetSymbolAddress((void**)&wl,  g_wl);

    cudaFuncSetAttribute(hgemm<0, true >, cudaFuncAttributeMaxDynamicSharedMemorySize, GSMEM);
    cudaFuncSetAttribute(hgemm<0, false>, cudaFuncAttributeMaxDynamicSharedMemorySize, GSMEM);
    cudaFuncSetAttribute(hgemm<1, true >, cudaFuncAttributeMaxDynamicSharedMemorySize, GSMEM);

    // ---- pack weights (split-bf16, [K/2][N] bf16x2) ----
    pack_w<<<dim3(MLPH / 256, GPAD / 2), 256>>>(w1, wh + OFF_MLP1, wl + OFF_MLP1, GDIM, MLPH);
    pack_w<<<dim3(DD / 256, MLPH / 2), 256>>>(w2, wh + OFF_MLP2, wl + OFF_MLP2, MLPH, DD);
    for (int i = 0; i < NBLK; i++) {
        size_t oq = OFF_QKV + (size_t)i * QKV_BLK;
        pack_w<<<dim3(DD / 256, DD / 2), 256>>>(wq + (size_t)i * DD * DD, wh + oq,                wl + oq,                DD, DD);
        pack_w<<<dim3(DD / 256, DD / 2), 256>>>(wk + (size_t)i * DD * DD, wh + oq + QKV_MAT,      wl + oq + QKV_MAT,      DD, DD);
        pack_w<<<dim3(DD / 256, DD / 2), 256>>>(wv + (size_t)i * DD * DD, wh + oq + 2 * QKV_MAT,  wl + oq + 2 * QKV_MAT,  DD, DD);
        size_t o1 = OFF_FF1 + (size_t)i * FF1_BLK;
        size_t o2 = OFF_FF2 + (size_t)i * FF2_BLK;
        pack_w<<<dim3(FFH / 256, DD / 2), 256>>>(fw1 + (size_t)i * DD * FFH, wh + o1, wl + o1, DD, FFH);
        pack_w<<<dim3(DD / 256, FFH / 2), 256>>>(fw2 + (size_t)i * FFH * DD, wh + o2, wl + o2, FFH, DD);
    }

    // ---- embedding + MLP + pos ----
    embed_gather<<<(NTOK * GDIM + 255) / 256, 256>>>(ids, emb);
    conv_xe<<<(NTOK * GPAD + 255) / 256, 256>>>();
    hgemm<1, true ><<<dim3(MLPH / 128, NTOK / 128), 256, GSMEM>>>(
        xeh, xel, wh + OFF_MLP1, wl + OFF_MLP1, b1, nullptr, h1h, h1l, NTOK, MLPH, GPAD);
    hgemm<0, false><<<dim3(DD / 128, NTOK / 128), 256, GSMEM>>>(
        h1h, h1l, wh + OFF_MLP2, wl + OFF_MLP2, b2, x, nullptr, nullptr, NTOK, DD, MLPH);
    add_pos<<<(NTOK * DD) / 256, 256>>>(pos);

    for (int i = 0; i < NBLK; i++) {
        size_t oq = OFF_QKV + (size_t)i * QKV_BLK;
        hgemm<0, true><<<dim3(DD / 128, NTOK / 128), 256, GSMEM>>>(
            xh, xl, wh + oq, wl + oq, bq + i * DD, q, nullptr, nullptr, NTOK, DD, DD);
        hgemm<0, true><<<dim3(DD / 128, NTOK / 128), 256, GSMEM>>>(
            xh, xl, wh + oq + QKV_MAT, wl + oq + QKV_MAT, bk + i * DD, k, nullptr, nullptr, NTOK, DD, DD);
        hgemm<0, true><<<dim3(DD / 128, NTOK / 128), 256, GSMEM>>>(
            xh, xl, wh + oq + 2 * QKV_MAT, wl + oq + 2 * QKV_MAT, bv + i * DD, v, nullptr, nullptr, NTOK, DD, DD);

        attn_scores<<<dim3(4, 4, BB * HH), 256>>>();
        softmax_kernel<<<(BB * HH * TTOK) / 8, 256>>>(smask, graph);
        attn_av<<<dim3(4, BB * HH), 256>>>();
        ln_res<<<NTOK, 256>>>(o, ln1g + i * DD, ln1b + i * DD);

        size_t o1 = OFF_FF1 + (size_t)i * FF1_BLK;
        size_t o2 = OFF_FF2 + (size_t)i * FF2_BLK;
        hgemm<1, true ><<<dim3(FFH / 128, NTOK / 128), 256, GSMEM>>>(
            xh, xl, wh + o1, wl + o1, fb1 + i * FFH, nullptr, ffh, ffl, NTOK, FFH, DD);
        hgemm<0, false><<<dim3(DD / 128, NTOK / 128), 256, GSMEM>>>(
            ffh, ffl, wh + o2, wl + o2, fb2 + i * DD, o, nullptr, nullptr, NTOK, DD, FFH);
        ln_res<<<NTOK, 256>>>(o, ln2g + i * DD, ln2b + i * DD);
    }

    cudaMemcpyAsync(d_out, x, sizeof(float) * NTOK * DD, cudaMemcpyDeviceToDevice);
}

// round 5
// speedup vs baseline: 2.9867x; 1.0264x over previous
#include <cuda_runtime.h>
#include <cuda_bf16.h>
#include <cstdint>

#define BB 16
#define TTOK 256
#define DD 1024
#define QKVW 3072
#define HH 16
#define NBLK 6
#define GDIM 300
#define GPAD 320
#define MLPH 2048
#define FFH 4096
#define DH 64
#define NTOK (BB*TTOK)   // 4096

// ---------------- scratch (device globals; no allocation allowed) ----------------
__device__ float g_xe [NTOK*GDIM];
__device__ float g_x  [NTOK*DD];
__device__ float g_qkv[(size_t)NTOK*QKVW];
__device__ float g_o  [NTOK*DD];
__device__ float g_s  [(size_t)BB*HH*TTOK*TTOK];
__device__ float g_bqkv[NBLK*QKVW];

// split-bf16 activations (hi/lo)
__device__ uint16_t g_xeh[NTOK*GPAD],  g_xel[NTOK*GPAD];
__device__ uint16_t g_xh [NTOK*DD],    g_xl [NTOK*DD];
__device__ uint16_t g_h1h[NTOK*MLPH],  g_h1l[NTOK*MLPH];
__device__ uint16_t g_ffh[(size_t)NTOK*FFH], g_ffl[(size_t)NTOK*FFH];

// packed split-bf16 weights: [K/2][N] uint32 (bf16x2 of k,k+1)
#define OFF_MLP1 0ull
#define OFF_MLP2 327680ull
#define OFF_QKV  1376256ull
#define QKV_BLK  1572864ull      // [512][3072]
#define OFF_FF1  10813440ull
#define FF1_BLK  2097152ull      // [512][4096]
#define OFF_FF2  23396352ull
#define FF2_BLK  2097152ull      // [2048][1024]
#define W_TOTAL  35979264ull
__device__ uint32_t g_wh[W_TOTAL];
__device__ uint32_t g_wl[W_TOTAL];

// ---------------- split helpers ----------------
__device__ __forceinline__ uint32_t pack_hi(float a, float b) {
    return __byte_perm(__float_as_uint(a), __float_as_uint(b), 0x7632);
}
__device__ __forceinline__ uint32_t pack_lo(float a, float b) {
    float ra = a - __uint_as_float(__float_as_uint(a) & 0xffff0000u);
    float rb = b - __uint_as_float(__float_as_uint(b) & 0xffff0000u);
    __nv_bfloat162 t = __floats2bfloat162_rn(ra, rb);
    return *reinterpret_cast<uint32_t*>(&t);
}
__device__ __forceinline__ uint16_t hi16(float v) {
    return (uint16_t)(__float_as_uint(v) >> 16);
}
__device__ __forceinline__ uint16_t lo16(float v) {
    float r = v - __uint_as_float(__float_as_uint(v) & 0xffff0000u);
    __nv_bfloat16 b = __float2bfloat16(r);
    return *reinterpret_cast<uint16_t*>(&b);
}

// ---------------- weight packing: W[K][Ns] fp32 -> [Kpad/2][Nd] hi/lo bf16x2 ----------------
__global__ void pack_w(const float* __restrict__ W, uint32_t* __restrict__ oh,
                       uint32_t* __restrict__ ol, int K, int Ns, int Nd) {
    int n  = blockIdx.x * 256 + threadIdx.x;
    int k2 = blockIdx.y;
    float a = (2 * k2     < K) ? W[(size_t)(2 * k2)     * Ns + n] : 0.f;
    float b = (2 * k2 + 1 < K) ? W[(size_t)(2 * k2 + 1) * Ns + n] : 0.f;
    oh[(size_t)k2 * Nd + n] = pack_hi(a, b);
    ol[(size_t)k2 * Nd + n] = pack_lo(a, b);
}

__global__ void pack_bias(const float* __restrict__ bq, const float* __restrict__ bk,
                          const float* __restrict__ bv) {
    int idx = blockIdx.x * 256 + threadIdx.x;
    if (idx >= NBLK * QKVW) return;
    int blk = idx / QKVW, n = idx - blk * QKVW;
    float v;
    if (n < DD)           v = bq[blk * DD + n];
    else if (n < 2 * DD)  v = bk[blk * DD + n - DD];
    else                  v = bv[blk * DD + n - 2 * DD];
    g_bqkv[idx] = v;
}

// ---------------- embedding gather + split-convert ----------------
__global__ void embed_gather(const int* __restrict__ ids, const float* __restrict__ emb) {
    int idx = blockIdx.x * blockDim.x + threadIdx.x;
    if (idx >= NTOK * GDIM) return;
    int bt = idx / GDIM;
    int c  = idx - bt * GDIM;
    g_xe[idx] = emb[(long long)ids[bt] * GDIM + c];
}
__global__ void conv_xe() {
    int idx = blockIdx.x * 256 + threadIdx.x;
    if (idx >= NTOK * GPAD) return;
    int m = idx / GPAD, k = idx - m * GPAD;
    float v = (k < GDIM) ? g_xe[m * GDIM + k] : 0.f;
    g_xeh[idx] = hi16(v);
    g_xel[idx] = lo16(v);
}

// ---------------- positional add (+ split write) ----------------
__global__ void add_pos(const float* __restrict__ pos) {
    int idx = blockIdx.x * blockDim.x + threadIdx.x;
    if (idx >= NTOK * DD) return;
    float v = g_x[idx] + pos[idx % (TTOK * DD)];
    g_x[idx] = v;
    g_xh[idx] = hi16(v);
    g_xl[idx] = lo16(v);
}

// ---------------- cp.async helpers ----------------
__device__ __forceinline__ uint32_t smem_u32(const void* p) {
    uint32_t a;
    asm("{ .reg .u64 t; cvta.to.shared.u64 t, %1; cvt.u32.u64 %0, t; }" : "=r"(a) : "l"(p));
    return a;
}
__device__ __forceinline__ void cp16(uint32_t saddr, const void* g) {
    asm volatile("cp.async.cg.shared.global [%0], [%1], 16;" :: "r"(saddr), "l"(g));
}
__device__ __forceinline__ void cp_commit() {
    asm volatile("cp.async.commit_group;" ::: "memory");
}
template<int N>
__device__ __forceinline__ void cp_wait() {
    asm volatile("cp.async.wait_group %0;" :: "n"(N) : "memory");
}

#define MMA_BF16(d, a, b)                                                        \
    asm volatile("mma.sync.aligned.m16n8k16.row.col.f32.bf16.bf16.f32 "          \
                 "{%0,%1,%2,%3},{%4,%5,%6,%7},{%8,%9},{%0,%1,%2,%3};"            \
                 : "+f"(d[0]), "+f"(d[1]), "+f"(d[2]), "+f"(d[3])                 \
                 : "r"(a[0]), "r"(a[1]), "r"(a[2]), "r"(a[3]), "r"(b[0]), "r"(b[1]))

// smem stage layout (bytes): Ah[128][40]bf16 @0 | Al @10240 | Wh[16][136]u32 @20480 | Wl @29184
#define STG_SZ 37888
#define NSTG 3
#define GSMEM (NSTG*STG_SZ)

// ---------------- split-bf16 HGEMM (pre-split operands) ----------------
// C = [relu](A @ W + bias). Tile 128x128x32, 4 warps of 64x64, 2 CTA/SM, 3-stage cp.async.
// MODE 0: write C fp32. MODE 1: write split bf16 (Ch,Cl).
template<int MODE, bool RELU>
__global__ void __launch_bounds__(128, 2)
hgemm(const uint16_t* __restrict__ Ah, const uint16_t* __restrict__ Al,
      const uint32_t* __restrict__ Wh, const uint32_t* __restrict__ Wl,
      const float* __restrict__ bias,
      float* __restrict__ C, uint16_t* __restrict__ Ch, uint16_t* __restrict__ Cl,
      int M, int N, int K) {
    extern __shared__ char smc[];
    const uint32_t smb = smem_u32(smc);
    const int tid  = threadIdx.x;
    const int lane = tid & 31, warp = tid >> 5;
    const int wm   = (warp >> 1) * 64;
    const int wn   = (warp & 1) * 64;
    const int group = lane >> 2, quad = lane & 3;
    const int row0 = blockIdx.y * 128;
    const int col0 = blockIdx.x * 128;

    float acc[4][8][4];
#pragma unroll
    for (int i = 0; i < 4; i++)
#pragma unroll
        for (int j = 0; j < 8; j++)
#pragma unroll
            for (int e = 0; e < 4; e++) acc[i][j][e] = 0.f;

    const int iters = K >> 5;

    auto fill = [&](int stage, int k0) {
        uint32_t sb = smb + stage * STG_SZ;
#pragma unroll
        for (int i = 0; i < 4; i++) {
            int c = tid + i * 128;
            int row = c >> 2, kc = c & 3;
            size_t g = (size_t)(row0 + row) * K + k0 + kc * 8;
            uint32_t so = sb + row * 80 + kc * 16;
            cp16(so, Ah + g);
            cp16(so + 10240, Al + g);
        }
        int k2b = k0 >> 1;
#pragma unroll
        for (int i = 0; i < 4; i++) {
            int c = tid + i * 128;
            int k2r = c >> 5, nch = c & 31;
            size_t g = (size_t)(k2b + k2r) * N + col0 + nch * 4;
            uint32_t so = sb + 20480 + k2r * 544 + nch * 16;
            cp16(so, Wh + g);
            cp16(so + 8704, Wl + g);
        }
    };

    auto compute = [&](int stage) {
        const uint16_t* sAh = (const uint16_t*)(smc + stage * STG_SZ);
        const uint16_t* sAl = (const uint16_t*)(smc + stage * STG_SZ + 10240);
        const uint32_t* sWh = (const uint32_t*)(smc + stage * STG_SZ + 20480);
        const uint32_t* sWl = (const uint32_t*)(smc + stage * STG_SZ + 29184);
#pragma unroll
        for (int ks = 0; ks < 2; ks++) {
            uint32_t bh[8][2], bl[8][2];
#pragma unroll
            for (int nt = 0; nt < 8; nt++) {
                int nc = wn + nt * 8 + group;
                bh[nt][0] = sWh[(ks * 8 + quad) * 136 + nc];
                bh[nt][1] = sWh[(ks * 8 + quad + 4) * 136 + nc];
                bl[nt][0] = sWl[(ks * 8 + quad) * 136 + nc];
                bl[nt][1] = sWl[(ks * 8 + quad + 4) * 136 + nc];
            }
#pragma unroll
            for (int mt = 0; mt < 4; mt++) {
                int r  = wm + mt * 16 + group;
                int kc = ks * 16 + quad * 2;
                uint32_t ah[4], al[4];
                ah[0] = *(const uint32_t*)&sAh[r * 40 + kc];
                ah[1] = *(const uint32_t*)&sAh[(r + 8) * 40 + kc];
                ah[2] = *(const uint32_t*)&sAh[r * 40 + kc + 8];
                ah[3] = *(const uint32_t*)&sAh[(r + 8) * 40 + kc + 8];
                al[0] = *(const uint32_t*)&sAl[r * 40 + kc];
                al[1] = *(const uint32_t*)&sAl[(r + 8) * 40 + kc];
                al[2] = *(const uint32_t*)&sAl[r * 40 + kc + 8];
                al[3] = *(const uint32_t*)&sAl[(r + 8) * 40 + kc + 8];
#pragma unroll
                for (int nt = 0; nt < 8; nt++) MMA_BF16(acc[mt][nt], ah, bh[nt]);
#pragma unroll
                for (int nt = 0; nt < 8; nt++) MMA_BF16(acc[mt][nt], al, bh[nt]);
#pragma unroll
                for (int nt = 0; nt < 8; nt++) MMA_BF16(acc[mt][nt], ah, bl[nt]);
            }
        }
    };

    fill(0, 0); cp_commit();
    if (iters > 1) { fill(1, 32); cp_commit(); }
    else cp_commit();

    for (int it = 0; it < iters; ++it) {
        if (it + 2 < iters) fill((it + 2) % NSTG, (it + 2) * 32);
        cp_commit();                       // group every iteration (may be empty)
        cp_wait<2>();
        __syncthreads();
        compute(it % NSTG);
        __syncthreads();
    }

    // ---- epilogue ----
#pragma unroll
    for (int mt = 0; mt < 4; mt++) {
        int r = row0 + wm + mt * 16 + group;
#pragma unroll
        for (int nt = 0; nt < 8; nt++) {
            int c  = col0 + wn + nt * 8 + quad * 2;
            float b0 = bias[c], b1 = bias[c + 1];
            float v0 = acc[mt][nt][0] + b0;
            float v1 = acc[mt][nt][1] + b1;
            float v2 = acc[mt][nt][2] + b0;
            float v3 = acc[mt][nt][3] + b1;
            if (RELU) {
                v0 = fmaxf(v0, 0.f); v1 = fmaxf(v1, 0.f);
                v2 = fmaxf(v2, 0.f); v3 = fmaxf(v3, 0.f);
            }
            if (MODE == 0) {
                *(float2*)&C[(size_t)r * N + c]       = make_float2(v0, v1);
                *(float2*)&C[(size_t)(r + 8) * N + c] = make_float2(v2, v3);
            } else {
                uint32_t* ChW = (uint32_t*)Ch;
                uint32_t* ClW = (uint32_t*)Cl;
                size_t i0 = ((size_t)r * N + c) >> 1;
                size_t i1 = ((size_t)(r + 8) * N + c) >> 1;
                ChW[i0] = pack_hi(v0, v1); ClW[i0] = pack_lo(v0, v1);
                ChW[i1] = pack_hi(v2, v3); ClW[i1] = pack_lo(v2, v3);
            }
        }
    }
}

// ---------------- attention scores: S = Q.K^T (from fused qkv buffer) ----------------
__global__ void __launch_bounds__(256) attn_scores() {
    const int bh = blockIdx.z;
    const int b  = bh >> 4, h = bh & 15;
    const int q0 = blockIdx.y * 64, n0 = blockIdx.x * 64;
    __shared__ float sQ[64][65];
    __shared__ float sK[64][65];
    const int tid = threadIdx.x;
    const float* Qp = g_qkv + (size_t)b * TTOK * QKVW + h * DH;
    const float* Kp = g_qkv + (size_t)b * TTOK * QKVW + DD + h * DH;
#pragma unroll
    for (int i = 0; i < 16; i++) {
        int e = tid + i * 256;
        int r = e >> 6, c = e & 63;
        sQ[r][c] = Qp[(size_t)(q0 + r) * QKVW + c];
        sK[r][c] = Kp[(size_t)(n0 + r) * QKVW + c];
    }
    __syncthreads();
    const int tr = tid >> 4, tc = tid & 15;
    float acc[4][4] = {};
#pragma unroll 8
    for (int kk = 0; kk < 64; kk++) {
        float rq[4], rk[4];
#pragma unroll
        for (int i = 0; i < 4; i++) rq[i] = sQ[tr * 4 + i][kk];
#pragma unroll
        for (int j = 0; j < 4; j++) rk[j] = sK[tc * 4 + j][kk];
#pragma unroll
        for (int i = 0; i < 4; i++)
#pragma unroll
            for (int j = 0; j < 4; j++)
                acc[i][j] = fmaf(rq[i], rk[j], acc[i][j]);
    }
    float* Sp = g_s + ((size_t)bh * TTOK + q0) * TTOK + n0;
#pragma unroll
    for (int i = 0; i < 4; i++)
        *(float4*)&Sp[(size_t)(tr * 4 + i) * TTOK + tc * 4] = *(float4*)&acc[i][0];
}

// ---------------- masked softmax ----------------
__global__ void __launch_bounds__(256) softmax_kernel(const int* __restrict__ smask,
                                                      const int* __restrict__ graph) {
    const int warp = threadIdx.x >> 5, lane = threadIdx.x & 31;
    const int r = blockIdx.x * 8 + warp;
    const int b = r >> 12;
    const int q = r & (TTOK - 1);
    float* row = g_s + (size_t)r * TTOK;
    const int* km = smask + b * TTOK;
    const int* gm = graph + ((size_t)b * TTOK + q) * TTOK;
    const float NEGF = -4294967295.0f;

    float v[8];
    float m = -3.4e38f;
#pragma unroll
    for (int j = 0; j < 8; j++) {
        int c = lane + j * 32;
        float s = row[c] * 0.125f;
        if (!(km[c] > 0 && gm[c] > 0)) s = NEGF;
        v[j] = s;
        m = fmaxf(m, s);
    }
#pragma unroll
    for (int off = 16; off >= 1; off >>= 1)
        m = fmaxf(m, __shfl_xor_sync(0xffffffffu, m, off));
    float sum = 0.f;
#pragma unroll
    for (int j = 0; j < 8; j++) {
        v[j] = expf(v[j] - m);
        sum += v[j];
    }
#pragma unroll
    for (int off = 16; off >= 1; off >>= 1)
        sum += __shfl_xor_sync(0xffffffffu, sum, off);
    float qs = (float)km[q];
    float inv = qs / sum;
#pragma unroll
    for (int j = 0; j < 8; j++)
        row[lane + j * 32] = v[j] * inv;
}

// ---------------- O = A @ V ----------------
__global__ void __launch_bounds__(256) attn_av() {
    const int bh = blockIdx.y;
    const int b  = bh >> 4, h = bh & 15;
    const int q0 = blockIdx.x * 64;
    __shared__ float sA[64][33];
    __shared__ float sV[32][64];
    const float* Ap = g_s + ((size_t)bh * TTOK + q0) * TTOK;
    const float* Vp = g_qkv + (size_t)b * TTOK * QKVW + 2 * DD + h * DH;
    const int tid = threadIdx.x, tr = tid >> 4, tc = tid & 15;
    float acc[4][4] = {};
    for (int k0 = 0; k0 < TTOK; k0 += 32) {
#pragma unroll
        for (int i = 0; i < 8; i++) {
            int e = tid + i * 256;
            int r = e >> 5, c = e & 31;
            sA[r][c] = Ap[(size_t)r * TTOK + k0 + c];
            int r2 = e >> 6, c2 = e & 63;
            sV[r2][c2] = Vp[(size_t)(k0 + r2) * QKVW + c2];
        }
        __syncthreads();
#pragma unroll
        for (int kk = 0; kk < 32; kk++) {
            float ra[4], rv[4];
#pragma unroll
            for (int i = 0; i < 4; i++) ra[i] = sA[tr * 4 + i][kk];
            *(float4*)rv = *(float4*)&sV[kk][tc * 4];
#pragma unroll
            for (int i = 0; i < 4; i++)
#pragma unroll
                for (int j = 0; j < 4; j++)
                    acc[i][j] = fmaf(ra[i], rv[j], acc[i][j]);
        }
        __syncthreads();
    }
    float* Op = g_o + ((size_t)(b * TTOK + q0)) * DD + h * DH;
#pragma unroll
    for (int i = 0; i < 4; i++)
        *(float4*)&Op[(size_t)(tr * 4 + i) * DD + tc * 4] = *(float4*)&acc[i][0];
}

// ---------------- residual + layernorm (+ split write) ----------------
__global__ void __launch_bounds__(256) ln_res(const float* __restrict__ addsrc,
                                              const float* __restrict__ gam,
                                              const float* __restrict__ bet) {
    const int row = blockIdx.x;
    const int tid = threadIdx.x;
    const int warp = tid >> 5, lane = tid & 31;
    float* xr = g_x + (size_t)row * DD;
    const float* ar = addsrc + (size_t)row * DD;
    __shared__ float red[8];

    float vals[4];
    float s = 0.f;
#pragma unroll
    for (int j = 0; j < 4; j++) {
        int c = tid + j * 256;
        vals[j] = xr[c] + ar[c];
        s += vals[j];
    }
#pragma unroll
    for (int off = 16; off >= 1; off >>= 1) s += __shfl_xor_sync(0xffffffffu, s, off);
    if (lane == 0) red[warp] = s;
    __syncthreads();
    float tot = 0.f;
#pragma unroll
    for (int w = 0; w < 8; w++) tot += red[w];
    const float mean = tot * (1.f / 1024.f);
    __syncthreads();

    float vs = 0.f;
#pragma unroll
    for (int j = 0; j < 4; j++) {
        float d = vals[j] - mean;
        vs += d * d;
    }
#pragma unroll
    for (int off = 16; off >= 1; off >>= 1) vs += __shfl_xor_sync(0xffffffffu, vs, off);
    if (lane == 0) red[warp] = vs;
    __syncthreads();
    float tot2 = 0.f;
#pragma unroll
    for (int w = 0; w < 8; w++) tot2 += red[w];
    const float var = tot2 * (1.f / 1024.f);
    const float rstd = rsqrtf(var + 1e-8f);

#pragma unroll
    for (int j = 0; j < 4; j++) {
        int c = tid + j * 256;
        float v = (vals[j] - mean) * rstd * gam[c] + bet[c];
        xr[c] = v;
        g_xh[(size_t)row * DD + c] = hi16(v);
        g_xl[(size_t)row * DD + c] = lo16(v);
    }
}

// ---------------- host orchestration ----------------
extern "C" void kernel_launch(void* const* d_in, const int* in_sizes, int n_in,
                              void* d_out, int out_size) {
    const int*   ids   = (const int*)d_in[0];
    const int*   smask = (const int*)d_in[1];
    const int*   graph = (const int*)d_in[2];
    const float* emb   = (const float*)d_in[3];
    const float* w1    = (const float*)d_in[4];
    const float* b1    = (const float*)d_in[5];
    const float* w2    = (const float*)d_in[6];
    const float* b2    = (const float*)d_in[7];
    const float* pos   = (const float*)d_in[8];
    const float* wq    = (const float*)d_in[9];
    const float* bq    = (const float*)d_in[10];
    const float* wk    = (const float*)d_in[11];
    const float* bk    = (const float*)d_in[12];
    const float* wv    = (const float*)d_in[13];
    const float* bv    = (const float*)d_in[14];
    const float* ln1g  = (const float*)d_in[15];
    const float* ln1b  = (const float*)d_in[16];
    const float* fw1   = (const float*)d_in[17];
    const float* fb1   = (const float*)d_in[18];
    const float* fw2   = (const float*)d_in[19];
    const float* fb2   = (const float*)d_in[20];
    const float* ln2g  = (const float*)d_in[21];
    const float* ln2b  = (const float*)d_in[22];

    float *x, *qkv, *o, *bqkvP;
    uint16_t *xeh, *xel, *xh, *xl, *h1h, *h1l, *ffh, *ffl;
    uint32_t *wh, *wl;
    cudaGetSymbolAddress((void**)&x,    g_x);
    cudaGetSymbolAddress((void**)&qkv,  g_qkv);
    cudaGetSymbolAddress((void**)&o,    g_o);
    cudaGetSymbolAddress((void**)&bqkvP,g_bqkv);
    cudaGetSymbolAddress((void**)&xeh,  g_xeh);
    cudaGetSymbolAddress((void**)&xel,  g_xel);
    cudaGetSymbolAddress((void**)&xh,   g_xh);
    cudaGetSymbolAddress((void**)&xl,   g_xl);
    cudaGetSymbolAddress((void**)&h1h,  g_h1h);
    cudaGetSymbolAddress((void**)&h1l,  g_h1l);
    cudaGetSymbolAddress((void**)&ffh,  g_ffh);
    cudaGetSymbolAddress((void**)&ffl,  g_ffl);
    cudaGetSymbolAddress((void**)&wh,   g_wh);
    cudaGetSymbolAddress((void**)&wl,   g_wl);

    cudaFuncSetAttribute(hgemm<0, true >, cudaFuncAttributeMaxDynamicSharedMemorySize, GSMEM);
    cudaFuncSetAttribute(hgemm<0, false>, cudaFuncAttributeMaxDynamicSharedMemorySize, GSMEM);
    cudaFuncSetAttribute(hgemm<1, true >, cudaFuncAttributeMaxDynamicSharedMemorySize, GSMEM);

    // launches 1-4: prep so launch #6 (ncu -s 5 -c 1) is a representative K=2048 GEMM
    embed_gather<<<(NTOK * GDIM + 255) / 256, 256>>>(ids, emb);                       // 1
    conv_xe<<<(NTOK * GPAD + 255) / 256, 256>>>();                                    // 2
    pack_w<<<dim3(MLPH / 256, GPAD / 2), 256>>>(w1, wh + OFF_MLP1, wl + OFF_MLP1, GDIM, MLPH, MLPH); // 3
    pack_w<<<dim3(DD / 256, MLPH / 2), 256>>>(w2, wh + OFF_MLP2, wl + OFF_MLP2, MLPH, DD, DD);       // 4
    hgemm<1, true ><<<dim3(MLPH / 128, NTOK / 128), 128, GSMEM>>>(                    // 5
        xeh, xel, wh + OFF_MLP1, wl + OFF_MLP1, b1, nullptr, h1h, h1l, NTOK, MLPH, GPAD);
    hgemm<0, false><<<dim3(DD / 128, NTOK / 128), 128, GSMEM>>>(                      // 6  <- profiled
        h1h, h1l, wh + OFF_MLP2, wl + OFF_MLP2, b2, x, nullptr, nullptr, NTOK, DD, MLPH);
    add_pos<<<(NTOK * DD) / 256, 256>>>(pos);

    // pack remaining weights (QKV fused into [K/2][3072])
    for (int i = 0; i < NBLK; i++) {
        size_t oq = OFF_QKV + (size_t)i * QKV_BLK;
        pack_w<<<dim3(DD / 256, DD / 2), 256>>>(wq + (size_t)i * DD * DD, wh + oq,          wl + oq,          DD, DD, QKVW);
        pack_w<<<dim3(DD / 256, DD / 2), 256>>>(wk + (size_t)i * DD * DD, wh + oq + DD,     wl + oq + DD,     DD, DD, QKVW);
        pack_w<<<dim3(DD / 256, DD / 2), 256>>>(wv + (size_t)i * DD * DD, wh + oq + 2 * DD, wl + oq + 2 * DD, DD, DD, QKVW);
        size_t o1 = OFF_FF1 + (size_t)i * FF1_BLK;
        size_t o2 = OFF_FF2 + (size_t)i * FF2_BLK;
        pack_w<<<dim3(FFH / 256, DD / 2), 256>>>(fw1 + (size_t)i * DD * FFH, wh + o1, wl + o1, DD, FFH, FFH);
        pack_w<<<dim3(DD / 256, FFH / 2), 256>>>(fw2 + (size_t)i * FFH * DD, wh + o2, wl + o2, FFH, DD, DD);
    }
    pack_bias<<<(NBLK * QKVW + 255) / 256, 256>>>(bq, bk, bv);

    for (int i = 0; i < NBLK; i++) {
        size_t oq = OFF_QKV + (size_t)i * QKV_BLK;
        hgemm<0, true><<<dim3(QKVW / 128, NTOK / 128), 128, GSMEM>>>(
            xh, xl, wh + oq, wl + oq, bqkvP + i * QKVW, qkv, nullptr, nullptr, NTOK, QKVW, DD);

        attn_scores<<<dim3(4, 4, BB * HH), 256>>>();
        softmax_kernel<<<(BB * HH * TTOK) / 8, 256>>>(smask, graph);
        attn_av<<<dim3(4, BB * HH), 256>>>();
        ln_res<<<NTOK, 256>>>(o, ln1g + i * DD, ln1b + i * DD);

        size_t o1 = OFF_FF1 + (size_t)i * FF1_BLK;
        size_t o2 = OFF_FF2 + (size_t)i * FF2_BLK;
        hgemm<1, true ><<<dim3(FFH / 128, NTOK / 128), 128, GSMEM>>>(
            xh, xl, wh + o1, wl + o1, fb1 + i * FFH, nullptr, ffh, ffl, NTOK, FFH, DD);
        hgemm<0, false><<<dim3(DD / 128, NTOK / 128), 128, GSMEM>>>(
            ffh, ffl, wh + o2, wl + o2, fb2 + i * DD, o, nullptr, nullptr, NTOK, DD, FFH);
        ln_res<<<NTOK, 256>>>(o, ln2g + i * DD, ln2b + i * DD);
    }

    cudaMemcpyAsync(d_out, x, sizeof(float) * NTOK * DD, cudaMemcpyDeviceToDevice);
}

// round 6
// speedup vs baseline: 3.0271x; 1.0135x over previous
#include <cuda_runtime.h>
#include <cuda_bf16.h>
#include <cstdint>

#define BB 16
#define TTOK 256
#define DD 1024
#define QKVW 3072
#define HH 16
#define NBLK 6
#define GDIM 300
#define GPAD 320
#define MLPH 2048
#define FFH 4096
#define DH 64
#define NTOK (BB*TTOK)   // 4096

// ---------------- scratch (device globals; no allocation allowed) ----------------
__device__ float g_xe [NTOK*GDIM];
__device__ float g_x  [NTOK*DD];
__device__ float g_qkv[(size_t)NTOK*QKVW];
__device__ float g_o  [NTOK*DD];
__device__ float g_s  [(size_t)BB*HH*TTOK*TTOK];
__device__ float g_bqkv[NBLK*QKVW];

// split-bf16 activations (hi/lo)
__device__ uint16_t g_xeh[NTOK*GPAD],  g_xel[NTOK*GPAD];
__device__ uint16_t g_xh [NTOK*DD],    g_xl [NTOK*DD];
__device__ uint16_t g_h1h[NTOK*MLPH],  g_h1l[NTOK*MLPH];
__device__ uint16_t g_ffh[(size_t)NTOK*FFH], g_ffl[(size_t)NTOK*FFH];

// packed split-bf16 weights, N-MAJOR: row n holds K/2 uint32 words (bf16x2 of k,k+1)
#define OFF_MLP1 0ull
#define OFF_MLP2 327680ull        // [2048 n][160 w]
#define OFF_QKV  1376256ull       // + [1024 n][1024 w]
#define QKV_BLK  1572864ull       // [3072 n][512 w]
#define OFF_FF1  10813440ull
#define FF1_BLK  2097152ull       // [4096 n][512 w]
#define OFF_FF2  23396352ull
#define FF2_BLK  2097152ull       // [1024 n][2048 w]
#define W_TOTAL  35979264ull
__device__ uint32_t g_wh[W_TOTAL];
__device__ uint32_t g_wl[W_TOTAL];

// ---------------- split helpers ----------------
__device__ __forceinline__ uint32_t pack_hi(float a, float b) {
    return __byte_perm(__float_as_uint(a), __float_as_uint(b), 0x7632);
}
__device__ __forceinline__ uint32_t pack_lo(float a, float b) {
    float ra = a - __uint_as_float(__float_as_uint(a) & 0xffff0000u);
    float rb = b - __uint_as_float(__float_as_uint(b) & 0xffff0000u);
    __nv_bfloat162 t = __floats2bfloat162_rn(ra, rb);
    return *reinterpret_cast<uint32_t*>(&t);
}
__device__ __forceinline__ uint16_t hi16(float v) {
    return (uint16_t)(__float_as_uint(v) >> 16);
}
__device__ __forceinline__ uint16_t lo16(float v) {
    float r = v - __uint_as_float(__float_as_uint(v) & 0xffff0000u);
    __nv_bfloat16 b = __float2bfloat16(r);
    return *reinterpret_cast<uint16_t*>(&b);
}

// ---------------- transpose-pack: W[K][N] fp32 -> n-major [N][Kpad/2] hi/lo bf16x2 ----------------
__global__ void pack_wt(const float* __restrict__ W, uint32_t* __restrict__ oh,
                        uint32_t* __restrict__ ol, int K, int N, int Kpad) {
    __shared__ float st[64][33];
    const int n0 = blockIdx.x * 32, k0 = blockIdx.y * 64;
    const int t = threadIdx.x;
    const int kk = t >> 5, n = t & 31;
#pragma unroll
    for (int i = 0; i < 8; i++) {
        int krow = k0 + kk + i * 8;
        st[kk + i * 8][n] = (krow < K) ? W[(size_t)krow * N + n0 + n] : 0.f;
    }
    __syncthreads();
    const int nn = t >> 3, c4 = (t & 7) * 4;
    uint32_t hv[4], lv[4];
#pragma unroll
    for (int j = 0; j < 4; j++) {
        int k2 = c4 + j;
        float a = st[2 * k2][nn], b = st[2 * k2 + 1][nn];
        hv[j] = pack_hi(a, b);
        lv[j] = pack_lo(a, b);
    }
    size_t o = (size_t)(n0 + nn) * (Kpad >> 1) + (k0 >> 1) + c4;
    *(uint4*)(oh + o) = make_uint4(hv[0], hv[1], hv[2], hv[3]);
    *(uint4*)(ol + o) = make_uint4(lv[0], lv[1], lv[2], lv[3]);
}

__global__ void pack_bias(const float* __restrict__ bq, const float* __restrict__ bk,
                          const float* __restrict__ bv) {
    int idx = blockIdx.x * 256 + threadIdx.x;
    if (idx >= NBLK * QKVW) return;
    int blk = idx / QKVW, n = idx - blk * QKVW;
    float v;
    if (n < DD)           v = bq[blk * DD + n];
    else if (n < 2 * DD)  v = bk[blk * DD + n - DD];
    else                  v = bv[blk * DD + n - 2 * DD];
    g_bqkv[idx] = v;
}

// ---------------- embedding gather + split-convert ----------------
__global__ void embed_gather(const int* __restrict__ ids, const float* __restrict__ emb) {
    int idx = blockIdx.x * blockDim.x + threadIdx.x;
    if (idx >= NTOK * GDIM) return;
    int bt = idx / GDIM;
    int c  = idx - bt * GDIM;
    g_xe[idx] = emb[(long long)ids[bt] * GDIM + c];
}
__global__ void conv_xe() {
    int idx = blockIdx.x * 256 + threadIdx.x;
    if (idx >= NTOK * GPAD) return;
    int m = idx / GPAD, k = idx - m * GPAD;
    float v = (k < GDIM) ? g_xe[m * GDIM + k] : 0.f;
    g_xeh[idx] = hi16(v);
    g_xel[idx] = lo16(v);
}

__global__ void add_pos(const float* __restrict__ pos) {
    int idx = blockIdx.x * blockDim.x + threadIdx.x;
    if (idx >= NTOK * DD) return;
    float v = g_x[idx] + pos[idx % (TTOK * DD)];
    g_x[idx] = v;
    g_xh[idx] = hi16(v);
    g_xl[idx] = lo16(v);
}

// ---------------- async / mma helpers ----------------
__device__ __forceinline__ uint32_t smem_u32(const void* p) {
    uint32_t a;
    asm("{ .reg .u64 t; cvta.to.shared.u64 t, %1; cvt.u32.u64 %0, t; }" : "=r"(a) : "l"(p));
    return a;
}
__device__ __forceinline__ void cp16(uint32_t saddr, const void* g) {
    asm volatile("cp.async.cg.shared.global [%0], [%1], 16;" :: "r"(saddr), "l"(g));
}
__device__ __forceinline__ void cp_commit() {
    asm volatile("cp.async.commit_group;" ::: "memory");
}
template<int N>
__device__ __forceinline__ void cp_wait() {
    asm volatile("cp.async.wait_group %0;" :: "n"(N) : "memory");
}

#define MMA_BF16(d, a, b)                                                        \
    asm volatile("mma.sync.aligned.m16n8k16.row.col.f32.bf16.bf16.f32 "          \
                 "{%0,%1,%2,%3},{%4,%5,%6,%7},{%8,%9},{%0,%1,%2,%3};"            \
                 : "+f"(d[0]), "+f"(d[1]), "+f"(d[2]), "+f"(d[3])                 \
                 : "r"(a[0]), "r"(a[1]), "r"(a[2]), "r"(a[3]), "r"(b[0]), "r"(b[1]))

#define LDSM4(r0, r1, r2, r3, addr)                                              \
    asm volatile("ldmatrix.sync.aligned.m8n8.x4.shared.b16 {%0,%1,%2,%3}, [%4];" \
                 : "=r"(r0), "=r"(r1), "=r"(r2), "=r"(r3) : "r"(addr))

// stage layout (bytes): Ah[128 m][40 hw] @0 | Al @10240 | Wh[128 n][20 w] @20480 | Wl @30720
#define STG_SZ 40960
#define NSTG 2
#define GSMEM (NSTG*STG_SZ)

// ---------------- split-bf16 HGEMM, ldmatrix-fed ----------------
// C = [relu](A @ W + bias). A: (Ah,Al) bf16 [M][K]; W: n-major packed (Wh,Wl) [N][K/2].
// Tile 128x128x32, 4 warps of 64x64, 2 CTA/SM, 2-stage cp.async.
// MODE 0: C fp32. MODE 1: split bf16 (Ch,Cl).
template<int MODE, bool RELU>
__global__ void __launch_bounds__(128, 2)
hgemm(const uint16_t* __restrict__ Ah, const uint16_t* __restrict__ Al,
      const uint32_t* __restrict__ Wh, const uint32_t* __restrict__ Wl,
      const float* __restrict__ bias,
      float* __restrict__ C, uint16_t* __restrict__ Ch, uint16_t* __restrict__ Cl,
      int M, int N, int K) {
    extern __shared__ char smc[];
    const uint32_t smb = smem_u32(smc);
    const int tid  = threadIdx.x;
    const int lane = tid & 31, warp = tid >> 5;
    const int wm   = (warp >> 1) * 64;
    const int wn   = (warp & 1) * 64;
    const int group = lane >> 2, quad = lane & 3;
    const int row0 = blockIdx.y * 128;
    const int col0 = blockIdx.x * 128;
    const int Kw   = K >> 1;              // words per W row

    // ldmatrix per-lane address components
    const int sub = lane >> 3, rr = lane & 7;
    const uint32_t aOff = ((wm + (sub & 1) * 8 + rr) * 40 + (sub >> 1) * 8) * 2;
    const uint32_t wOff = 20480u + ((wn + (sub >> 1) * 8 + rr) * 20 + (sub & 1) * 4) * 4;

    float acc[4][8][4];
#pragma unroll
    for (int i = 0; i < 4; i++)
#pragma unroll
        for (int j = 0; j < 8; j++)
#pragma unroll
            for (int e = 0; e < 4; e++) acc[i][j][e] = 0.f;

    const int iters = K >> 5;

    auto fill = [&](int stage, int k0) {
        uint32_t sb = smb + stage * STG_SZ;
#pragma unroll
        for (int i = 0; i < 4; i++) {          // A: 128 rows x 32 k (hi+lo)
            int c = tid + i * 128;
            int row = c >> 2, kc = c & 3;
            size_t g = (size_t)(row0 + row) * K + k0 + kc * 8;
            uint32_t so = sb + row * 80 + kc * 16;
            cp16(so, Ah + g);
            cp16(so + 10240, Al + g);
        }
        const int k2b = k0 >> 1;
#pragma unroll
        for (int i = 0; i < 4; i++) {          // W: 128 n-rows x 16 words (hi+lo)
            int c = tid + i * 128;
            int row = c >> 2, ch = c & 3;
            size_t g = (size_t)(col0 + row) * Kw + k2b + ch * 4;
            uint32_t so = sb + 20480 + row * 80 + ch * 16;
            cp16(so, Wh + g);
            cp16(so + 10240, Wl + g);
        }
    };

    auto compute = [&](int stage) {
        const uint32_t aBase = smb + stage * STG_SZ + aOff;
        const uint32_t wBase = smb + stage * STG_SZ + wOff;
#pragma unroll
        for (int ks = 0; ks < 2; ks++) {
            uint32_t wh_[4][4], wl_[4][4];
#pragma unroll
            for (int p = 0; p < 4; p++) {
                LDSM4(wh_[p][0], wh_[p][1], wh_[p][2], wh_[p][3], wBase + p * 1280 + ks * 32);
                LDSM4(wl_[p][0], wl_[p][1], wl_[p][2], wl_[p][3], wBase + 10240 + p * 1280 + ks * 32);
            }
#pragma unroll
            for (int mt = 0; mt < 4; mt++) {
                uint32_t ah[4], al[4];
                LDSM4(ah[0], ah[1], ah[2], ah[3], aBase + mt * 1280 + ks * 32);
                LDSM4(al[0], al[1], al[2], al[3], aBase + 10240 + mt * 1280 + ks * 32);
#pragma unroll
                for (int nt = 0; nt < 8; nt++) MMA_BF16(acc[mt][nt], ah, (&wh_[nt >> 1][(nt & 1) * 2]));
#pragma unroll
                for (int nt = 0; nt < 8; nt++) MMA_BF16(acc[mt][nt], al, (&wh_[nt >> 1][(nt & 1) * 2]));
#pragma unroll
                for (int nt = 0; nt < 8; nt++) MMA_BF16(acc[mt][nt], ah, (&wl_[nt >> 1][(nt & 1) * 2]));
            }
        }
    };

    fill(0, 0); cp_commit();

    for (int it = 0; it < iters; ++it) {
        if (it + 1 < iters) { fill((it + 1) & 1, (it + 1) * 32); cp_commit(); cp_wait<1>(); }
        else cp_wait<0>();
        __syncthreads();
        compute(it & 1);
        __syncthreads();
    }

    // ---- epilogue ----
#pragma unroll
    for (int mt = 0; mt < 4; mt++) {
        int r = row0 + wm + mt * 16 + group;
#pragma unroll
        for (int nt = 0; nt < 8; nt++) {
            int c  = col0 + wn + nt * 8 + quad * 2;
            float b0 = bias[c], b1 = bias[c + 1];
            float v0 = acc[mt][nt][0] + b0;
            float v1 = acc[mt][nt][1] + b1;
            float v2 = acc[mt][nt][2] + b0;
            float v3 = acc[mt][nt][3] + b1;
            if (RELU) {
                v0 = fmaxf(v0, 0.f); v1 = fmaxf(v1, 0.f);
                v2 = fmaxf(v2, 0.f); v3 = fmaxf(v3, 0.f);
            }
            if (MODE == 0) {
                *(float2*)&C[(size_t)r * N + c]       = make_float2(v0, v1);
                *(float2*)&C[(size_t)(r + 8) * N + c] = make_float2(v2, v3);
            } else {
                uint32_t* ChW = (uint32_t*)Ch;
                uint32_t* ClW = (uint32_t*)Cl;
                size_t i0 = ((size_t)r * N + c) >> 1;
                size_t i1 = ((size_t)(r + 8) * N + c) >> 1;
                ChW[i0] = pack_hi(v0, v1); ClW[i0] = pack_lo(v0, v1);
                ChW[i1] = pack_hi(v2, v3); ClW[i1] = pack_lo(v2, v3);
            }
        }
    }
}

// ---------------- attention scores: S = Q.K^T ----------------
__global__ void __launch_bounds__(256) attn_scores() {
    const int bh = blockIdx.z;
    const int b  = bh >> 4, h = bh & 15;
    const int q0 = blockIdx.y * 64, n0 = blockIdx.x * 64;
    __shared__ float sQ[64][65];
    __shared__ float sK[64][65];
    const int tid = threadIdx.x;
    const float* Qp = g_qkv + (size_t)b * TTOK * QKVW + h * DH;
    const float* Kp = g_qkv + (size_t)b * TTOK * QKVW + DD + h * DH;
#pragma unroll
    for (int i = 0; i < 16; i++) {
        int e = tid + i * 256;
        int r = e >> 6, c = e & 63;
        sQ[r][c] = Qp[(size_t)(q0 + r) * QKVW + c];
        sK[r][c] = Kp[(size_t)(n0 + r) * QKVW + c];
    }
    __syncthreads();
    const int tr = tid >> 4, tc = tid & 15;
    float acc[4][4] = {};
#pragma unroll 8
    for (int kk = 0; kk < 64; kk++) {
        float rq[4], rk[4];
#pragma unroll
        for (int i = 0; i < 4; i++) rq[i] = sQ[tr * 4 + i][kk];
#pragma unroll
        for (int j = 0; j < 4; j++) rk[j] = sK[tc * 4 + j][kk];
#pragma unroll
        for (int i = 0; i < 4; i++)
#pragma unroll
            for (int j = 0; j < 4; j++)
                acc[i][j] = fmaf(rq[i], rk[j], acc[i][j]);
    }
    float* Sp = g_s + ((size_t)bh * TTOK + q0) * TTOK + n0;
#pragma unroll
    for (int i = 0; i < 4; i++)
        *(float4*)&Sp[(size_t)(tr * 4 + i) * TTOK + tc * 4] = *(float4*)&acc[i][0];
}

// ---------------- masked softmax ----------------
__global__ void __launch_bounds__(256) softmax_kernel(const int* __restrict__ smask,
                                                      const int* __restrict__ graph) {
    const int warp = threadIdx.x >> 5, lane = threadIdx.x & 31;
    const int r = blockIdx.x * 8 + warp;
    const int b = r >> 12;
    const int q = r & (TTOK - 1);
    float* row = g_s + (size_t)r * TTOK;
    const int* km = smask + b * TTOK;
    const int* gm = graph + ((size_t)b * TTOK + q) * TTOK;
    const float NEGF = -4294967295.0f;

    float v[8];
    float m = -3.4e38f;
#pragma unroll
    for (int j = 0; j < 8; j++) {
        int c = lane + j * 32;
        float s = row[c] * 0.125f;
        if (!(km[c] > 0 && gm[c] > 0)) s = NEGF;
        v[j] = s;
        m = fmaxf(m, s);
    }
#pragma unroll
    for (int off = 16; off >= 1; off >>= 1)
        m = fmaxf(m, __shfl_xor_sync(0xffffffffu, m, off));
    float sum = 0.f;
#pragma unroll
    for (int j = 0; j < 8; j++) {
        v[j] = expf(v[j] - m);
        sum += v[j];
    }
#pragma unroll
    for (int off = 16; off >= 1; off >>= 1)
        sum += __shfl_xor_sync(0xffffffffu, sum, off);
    float qs = (float)km[q];
    float inv = qs / sum;
#pragma unroll
    for (int j = 0; j < 8; j++)
        row[lane + j * 32] = v[j] * inv;
}

// ---------------- O = A @ V ----------------
__global__ void __launch_bounds__(256) attn_av() {
    const int bh = blockIdx.y;
    const int b  = bh >> 4, h = bh & 15;
    const int q0 = blockIdx.x * 64;
    __shared__ float sA[64][33];
    __shared__ float sV[32][64];
    const float* Ap = g_s + ((size_t)bh * TTOK + q0) * TTOK;
    const float* Vp = g_qkv + (size_t)b * TTOK * QKVW + 2 * DD + h * DH;
    const int tid = threadIdx.x, tr = tid >> 4, tc = tid & 15;
    float acc[4][4] = {};
    for (int k0 = 0; k0 < TTOK; k0 += 32) {
#pragma unroll
        for (int i = 0; i < 8; i++) {
            int e = tid + i * 256;
            int r = e >> 5, c = e & 31;
            sA[r][c] = Ap[(size_t)r * TTOK + k0 + c];
            int r2 = e >> 6, c2 = e & 63;
            sV[r2][c2] = Vp[(size_t)(k0 + r2) * QKVW + c2];
        }
        __syncthreads();
#pragma unroll
        for (int kk = 0; kk < 32; kk++) {
            float ra[4], rv[4];
#pragma unroll
            for (int i = 0; i < 4; i++) ra[i] = sA[tr * 4 + i][kk];
            *(float4*)rv = *(float4*)&sV[kk][tc * 4];
#pragma unroll
            for (int i = 0; i < 4; i++)
#pragma unroll
                for (int j = 0; j < 4; j++)
                    acc[i][j] = fmaf(ra[i], rv[j], acc[i][j]);
        }
        __syncthreads();
    }
    float* Op = g_o + ((size_t)(b * TTOK + q0)) * DD + h * DH;
#pragma unroll
    for (int i = 0; i < 4; i++)
        *(float4*)&Op[(size_t)(tr * 4 + i) * DD + tc * 4] = *(float4*)&acc[i][0];
}

// ---------------- residual + layernorm (+ split write) ----------------
__global__ void __launch_bounds__(256) ln_res(const float* __restrict__ addsrc,
                                              const float* __restrict__ gam,
                                              const float* __restrict__ bet) {
    const int row = blockIdx.x;
    const int tid = threadIdx.x;
    const int warp = tid >> 5, lane = tid & 31;
    float* xr = g_x + (size_t)row * DD;
    const float* ar = addsrc + (size_t)row * DD;
    __shared__ float red[8];

    float vals[4];
    float s = 0.f;
#pragma unroll
    for (int j = 0; j < 4; j++) {
        int c = tid + j * 256;
        vals[j] = xr[c] + ar[c];
        s += vals[j];
    }
#pragma unroll
    for (int off = 16; off >= 1; off >>= 1) s += __shfl_xor_sync(0xffffffffu, s, off);
    if (lane == 0) red[warp] = s;
    __syncthreads();
    float tot = 0.f;
#pragma unroll
    for (int w = 0; w < 8; w++) tot += red[w];
    const float mean = tot * (1.f / 1024.f);
    __syncthreads();

    float vs = 0.f;
#pragma unroll
    for (int j = 0; j < 4; j++) {
        float d = vals[j] - mean;
        vs += d * d;
    }
#pragma unroll
    for (int off = 16; off >= 1; off >>= 1) vs += __shfl_xor_sync(0xffffffffu, vs, off);
    if (lane == 0) red[warp] = vs;
    __syncthreads();
    float tot2 = 0.f;
#pragma unroll
    for (int w = 0; w < 8; w++) tot2 += red[w];
    const float var = tot2 * (1.f / 1024.f);
    const float rstd = rsqrtf(var + 1e-8f);

#pragma unroll
    for (int j = 0; j < 4; j++) {
        int c = tid + j * 256;
        float v = (vals[j] - mean) * rstd * gam[c] + bet[c];
        xr[c] = v;
        g_xh[(size_t)row * DD + c] = hi16(v);
        g_xl[(size_t)row * DD + c] = lo16(v);
    }
}

// ---------------- host orchestration ----------------
extern "C" void kernel_launch(void* const* d_in, const int* in_sizes, int n_in,
                              void* d_out, int out_size) {
    const int*   ids   = (const int*)d_in[0];
    const int*   smask = (const int*)d_in[1];
    const int*   graph = (const int*)d_in[2];
    const float* emb   = (const float*)d_in[3];
    const float* w1    = (const float*)d_in[4];
    const float* b1    = (const float*)d_in[5];
    const float* w2    = (const float*)d_in[6];
    const float* b2    = (const float*)d_in[7];
    const float* pos   = (const float*)d_in[8];
    const float* wq    = (const float*)d_in[9];
    const float* bq    = (const float*)d_in[10];
    const float* wk    = (const float*)d_in[11];
    const float* bk    = (const float*)d_in[12];
    const float* wv    = (const float*)d_in[13];
    const float* bv    = (const float*)d_in[14];
    const float* ln1g  = (const float*)d_in[15];
    const float* ln1b  = (const float*)d_in[16];
    const float* fw1   = (const float*)d_in[17];
    const float* fb1   = (const float*)d_in[18];
    const float* fw2   = (const float*)d_in[19];
    const float* fb2   = (const float*)d_in[20];
    const float* ln2g  = (const float*)d_in[21];
    const float* ln2b  = (const float*)d_in[22];

    float *x, *qkv, *o, *bqkvP;
    uint16_t *xeh, *xel, *xh, *xl, *h1h, *h1l, *ffh, *ffl;
    uint32_t *wh, *wl;
    cudaGetSymbolAddress((void**)&x,    g_x);
    cudaGetSymbolAddress((void**)&qkv,  g_qkv);
    cudaGetSymbolAddress((void**)&o,    g_o);
    cudaGetSymbolAddress((void**)&bqkvP,g_bqkv);
    cudaGetSymbolAddress((void**)&xeh,  g_xeh);
    cudaGetSymbolAddress((void**)&xel,  g_xel);
    cudaGetSymbolAddress((void**)&xh,   g_xh);
    cudaGetSymbolAddress((void**)&xl,   g_xl);
    cudaGetSymbolAddress((void**)&h1h,  g_h1h);
    cudaGetSymbolAddress((void**)&h1l,  g_h1l);
    cudaGetSymbolAddress((void**)&ffh,  g_ffh);
    cudaGetSymbolAddress((void**)&ffl,  g_ffl);
    cudaGetSymbolAddress((void**)&wh,   g_wh);
    cudaGetSymbolAddress((void**)&wl,   g_wl);

    cudaFuncSetAttribute(hgemm<0, true >, cudaFuncAttributeMaxDynamicSharedMemorySize, GSMEM);
    cudaFuncSetAttribute(hgemm<0, false>, cudaFuncAttributeMaxDynamicSharedMemorySize, GSMEM);
    cudaFuncSetAttribute(hgemm<1, true >, cudaFuncAttributeMaxDynamicSharedMemorySize, GSMEM);

    // launches 1-5 are prep so launch #6 (ncu -s 5 -c 1) is a representative K=2048 GEMM
    embed_gather<<<(NTOK * GDIM + 255) / 256, 256>>>(ids, emb);                          // 1
    conv_xe<<<(NTOK * GPAD + 255) / 256, 256>>>();                                       // 2
    pack_wt<<<dim3(MLPH / 32, GPAD / 64), 256>>>(w1, wh + OFF_MLP1, wl + OFF_MLP1, GDIM, MLPH, GPAD);  // 3
    pack_wt<<<dim3(DD / 32, MLPH / 64), 256>>>(w2, wh + OFF_MLP2, wl + OFF_MLP2, MLPH, DD, MLPH);      // 4
    hgemm<1, true ><<<dim3(MLPH / 128, NTOK / 128), 128, GSMEM>>>(                       // 5
        xeh, xel, wh + OFF_MLP1, wl + OFF_MLP1, b1, nullptr, h1h, h1l, NTOK, MLPH, GPAD);
    hgemm<0, false><<<dim3(DD / 128, NTOK / 128), 128, GSMEM>>>(                         // 6 <- profiled
        h1h, h1l, wh + OFF_MLP2, wl + OFF_MLP2, b2, x, nullptr, nullptr, NTOK, DD, MLPH);
    add_pos<<<(NTOK * DD) / 256, 256>>>(pos);

    // pack remaining weights: QKV fused n-major rows [0..3071] with per-matrix row offsets
    for (int i = 0; i < NBLK; i++) {
        size_t oq = OFF_QKV + (size_t)i * QKV_BLK;
        pack_wt<<<dim3(DD / 32, DD / 64), 256>>>(wq + (size_t)i * DD * DD, wh + oq,                      wl + oq,                      DD, DD, DD);
        pack_wt<<<dim3(DD / 32, DD / 64), 256>>>(wk + (size_t)i * DD * DD, wh + oq + (size_t)DD * DD / 2,     wl + oq + (size_t)DD * DD / 2,     DD, DD, DD);
        pack_wt<<<dim3(DD / 32, DD / 64), 256>>>(wv + (size_t)i * DD * DD, wh + oq + (size_t)DD * DD,         wl + oq + (size_t)DD * DD,         DD, DD, DD);
        size_t o1 = OFF_FF1 + (size_t)i * FF1_BLK;
        size_t o2 = OFF_FF2 + (size_t)i * FF2_BLK;
        pack_wt<<<dim3(FFH / 32, DD / 64), 256>>>(fw1 + (size_t)i * DD * FFH, wh + o1, wl + o1, DD, FFH, DD);
        pack_wt<<<dim3(DD / 32, FFH / 64), 256>>>(fw2 + (size_t)i * FFH * DD, wh + o2, wl + o2, FFH, DD, FFH);
    }
    pack_bias<<<(NBLK * QKVW + 255) / 256, 256>>>(bq, bk, bv);

    for (int i = 0; i < NBLK; i++) {
        size_t oq = OFF_QKV + (size_t)i * QKV_BLK;
        hgemm<0, true><<<dim3(QKVW / 128, NTOK / 128), 128, GSMEM>>>(
            xh, xl, wh + oq, wl + oq, bqkvP + i * QKVW, qkv, nullptr, nullptr, NTOK, QKVW, DD);

        attn_scores<<<dim3(4, 4, BB * HH), 256>>>();
        softmax_kernel<<<(BB * HH * TTOK) / 8, 256>>>(smask, graph);
        attn_av<<<dim3(4, BB * HH), 256>>>();
        ln_res<<<NTOK, 256>>>(o, ln1g + i * DD, ln1b + i * DD);

        size_t o1 = OFF_FF1 + (size_t)i * FF1_BLK;
        size_t o2 = OFF_FF2 + (size_t)i * FF2_BLK;
        hgemm<1, true ><<<dim3(FFH / 128, NTOK / 128), 128, GSMEM>>>(
            xh, xl, wh + o1, wl + o1, fb1 + i * FFH, nullptr, ffh, ffl, NTOK, FFH, DD);
        hgemm<0, false><<<dim3(DD / 128, NTOK / 128), 128, GSMEM>>>(
            ffh, ffl, wh + o2, wl + o2, fb2 + i * DD, o, nullptr, nullptr, NTOK, DD, FFH);
        ln_res<<<NTOK, 256>>>(o, ln2g + i * DD, ln2b + i * DD);
    }

    cudaMemcpyAsync(d_out, x, sizeof(float) * NTOK * DD, cudaMemcpyDeviceToDevice);
}

// round 7
// speedup vs baseline: 3.0411x; 1.0046x over previous
#include <cuda_runtime.h>
#include <cuda_bf16.h>
#include <cstdint>

#define BB 16
#define TTOK 256
#define DD 1024
#define QKVW 3072
#define HH 16
#define NBLK 6
#define GDIM 300
#define GPAD 320
#define MLPH 2048
#define FFH 4096
#define DH 64
#define NTOK (BB*TTOK)   // 4096

// ---------------- scratch (device globals; no allocation allowed) ----------------
__device__ float g_xe [NTOK*GDIM];
__device__ float g_x  [NTOK*DD];
__device__ float g_o  [NTOK*DD];
__device__ float g_s  [(size_t)BB*HH*TTOK*TTOK];
__device__ float g_bqkv[NBLK*QKVW];

// split-bf16 activations (hi/lo)
__device__ __align__(16) uint16_t g_xeh[NTOK*GPAD],  g_xel[NTOK*GPAD];
__device__ __align__(16) uint16_t g_xh [NTOK*DD],    g_xl [NTOK*DD];
__device__ __align__(16) uint16_t g_h1h[NTOK*MLPH],  g_h1l[NTOK*MLPH];
__device__ __align__(16) uint16_t g_ffh[(size_t)NTOK*FFH], g_ffl[(size_t)NTOK*FFH];
__device__ __align__(16) uint16_t g_qkvh[(size_t)NTOK*QKVW], g_qkvl[(size_t)NTOK*QKVW];
__device__ __align__(16) uint16_t g_ph[(size_t)BB*HH*TTOK*TTOK], g_pl[(size_t)BB*HH*TTOK*TTOK];
// V transposed per (b,h): [z][dh=64][keys/2=128 words]
__device__ uint32_t g_vth[(size_t)BB*HH*DH*(TTOK/2)];
__device__ uint32_t g_vtl[(size_t)BB*HH*DH*(TTOK/2)];

// packed split-bf16 weights, N-MAJOR: row n holds K/2 uint32 words (bf16x2 of k,k+1)
#define OFF_MLP1 0ull
#define OFF_MLP2 327680ull
#define OFF_QKV  1376256ull
#define QKV_BLK  1572864ull
#define OFF_FF1  10813440ull
#define FF1_BLK  2097152ull
#define OFF_FF2  23396352ull
#define FF2_BLK  2097152ull
#define W_TOTAL  35979264ull
__device__ uint32_t g_wh[W_TOTAL];
__device__ uint32_t g_wl[W_TOTAL];

// ---------------- split helpers ----------------
__device__ __forceinline__ uint32_t pack_hi(float a, float b) {
    return __byte_perm(__float_as_uint(a), __float_as_uint(b), 0x7632);
}
__device__ __forceinline__ uint32_t pack_lo(float a, float b) {
    float ra = a - __uint_as_float(__float_as_uint(a) & 0xffff0000u);
    float rb = b - __uint_as_float(__float_as_uint(b) & 0xffff0000u);
    __nv_bfloat162 t = __floats2bfloat162_rn(ra, rb);
    return *reinterpret_cast<uint32_t*>(&t);
}
__device__ __forceinline__ uint16_t hi16(float v) {
    return (uint16_t)(__float_as_uint(v) >> 16);
}
__device__ __forceinline__ uint16_t lo16(float v) {
    float r = v - __uint_as_float(__float_as_uint(v) & 0xffff0000u);
    __nv_bfloat16 b = __float2bfloat16(r);
    return *reinterpret_cast<uint16_t*>(&b);
}

// ---------------- transpose-pack: W[K][N] fp32 -> n-major [N][Kpad/2] hi/lo bf16x2 ----------------
__global__ void pack_wt(const float* __restrict__ W, uint32_t* __restrict__ oh,
                        uint32_t* __restrict__ ol, int K, int N, int Kpad) {
    __shared__ float st[64][33];
    const int n0 = blockIdx.x * 32, k0 = blockIdx.y * 64;
    const int t = threadIdx.x;
    const int kk = t >> 5, n = t & 31;
#pragma unroll
    for (int i = 0; i < 8; i++) {
        int krow = k0 + kk + i * 8;
        st[kk + i * 8][n] = (krow < K) ? W[(size_t)krow * N + n0 + n] : 0.f;
    }
    __syncthreads();
    const int nn = t >> 3, c4 = (t & 7) * 4;
    uint32_t hv[4], lv[4];
#pragma unroll
    for (int j = 0; j < 4; j++) {
        int k2 = c4 + j;
        float a = st[2 * k2][nn], b = st[2 * k2 + 1][nn];
        hv[j] = pack_hi(a, b);
        lv[j] = pack_lo(a, b);
    }
    size_t o = (size_t)(n0 + nn) * (Kpad >> 1) + (k0 >> 1) + c4;
    *(uint4*)(oh + o) = make_uint4(hv[0], hv[1], hv[2], hv[3]);
    *(uint4*)(ol + o) = make_uint4(lv[0], lv[1], lv[2], lv[3]);
}

__global__ void pack_bias(const float* __restrict__ bq, const float* __restrict__ bk,
                          const float* __restrict__ bv) {
    int idx = blockIdx.x * 256 + threadIdx.x;
    if (idx >= NBLK * QKVW) return;
    int blk = idx / QKVW, n = idx - blk * QKVW;
    float v;
    if (n < DD)           v = bq[blk * DD + n];
    else if (n < 2 * DD)  v = bk[blk * DD + n - DD];
    else                  v = bv[blk * DD + n - 2 * DD];
    g_bqkv[idx] = v;
}

// ---------------- embedding gather + split-convert ----------------
__global__ void embed_gather(const int* __restrict__ ids, const float* __restrict__ emb) {
    int idx = blockIdx.x * blockDim.x + threadIdx.x;
    if (idx >= NTOK * GDIM) return;
    int bt = idx / GDIM;
    int c  = idx - bt * GDIM;
    g_xe[idx] = emb[(long long)ids[bt] * GDIM + c];
}
__global__ void conv_xe() {
    int idx = blockIdx.x * 256 + threadIdx.x;
    if (idx >= NTOK * GPAD) return;
    int m = idx / GPAD, k = idx - m * GPAD;
    float v = (k < GDIM) ? g_xe[m * GDIM + k] : 0.f;
    g_xeh[idx] = hi16(v);
    g_xel[idx] = lo16(v);
}

__global__ void add_pos(const float* __restrict__ pos) {
    int idx = blockIdx.x * blockDim.x + threadIdx.x;
    if (idx >= NTOK * DD) return;
    float v = g_x[idx] + pos[idx % (TTOK * DD)];
    g_x[idx] = v;
    g_xh[idx] = hi16(v);
    g_xl[idx] = lo16(v);
}

// ---------------- V transpose: qkv split V section -> [z][dh][key/2 words] ----------------
__global__ void __launch_bounds__(256) v_trans() {
    __shared__ uint16_t sh[64][65], sl[64][65];
    const int kt = blockIdx.x, z = blockIdx.y;
    const int zb = z >> 4, zh = z & 15;
    const int t = threadIdx.x;
    const size_t base = (size_t)zb * TTOK * QKVW + 2 * DD + (size_t)zh * DH;
#pragma unroll
    for (int i = 0; i < 16; i++) {
        int e = t + i * 256;
        int r = e >> 6, c = e & 63;
        size_t g = base + (size_t)(kt * 64 + r) * QKVW + c;
        sh[r][c] = g_qkvh[g];
        sl[r][c] = g_qkvl[g];
    }
    __syncthreads();
    const int d = t >> 2, w0 = (t & 3) * 8;
    size_t ob = (size_t)z * (DH * TTOK / 2) + (size_t)d * (TTOK / 2) + kt * 32;
#pragma unroll
    for (int j = 0; j < 8; j++) {
        int w = w0 + j;
        g_vth[ob + w] = (uint32_t)sh[2 * w][d] | ((uint32_t)sh[2 * w + 1][d] << 16);
        g_vtl[ob + w] = (uint32_t)sl[2 * w][d] | ((uint32_t)sl[2 * w + 1][d] << 16);
    }
}

// ---------------- async / mma helpers ----------------
__device__ __forceinline__ uint32_t smem_u32(const void* p) {
    uint32_t a;
    asm("{ .reg .u64 t; cvta.to.shared.u64 t, %1; cvt.u32.u64 %0, t; }" : "=r"(a) : "l"(p));
    return a;
}
__device__ __forceinline__ void cp16(uint32_t saddr, const void* g) {
    asm volatile("cp.async.cg.shared.global [%0], [%1], 16;" :: "r"(saddr), "l"(g));
}
__device__ __forceinline__ void cp_commit() {
    asm volatile("cp.async.commit_group;" ::: "memory");
}
template<int N>
__device__ __forceinline__ void cp_wait() {
    asm volatile("cp.async.wait_group %0;" :: "n"(N) : "memory");
}

#define MMA_BF16(d, a, b)                                                        \
    asm volatile("mma.sync.aligned.m16n8k16.row.col.f32.bf16.bf16.f32 "          \
                 "{%0,%1,%2,%3},{%4,%5,%6,%7},{%8,%9},{%0,%1,%2,%3};"            \
                 : "+f"(d[0]), "+f"(d[1]), "+f"(d[2]), "+f"(d[3])                 \
                 : "r"(a[0]), "r"(a[1]), "r"(a[2]), "r"(a[3]), "r"(b[0]), "r"(b[1]))

#define LDSM4(r0, r1, r2, r3, addr)                                              \
    asm volatile("ldmatrix.sync.aligned.m8n8.x4.shared.b16 {%0,%1,%2,%3}, [%4];" \
                 : "=r"(r0), "=r"(r1), "=r"(r2), "=r"(r3) : "r"(addr))

// ---------------- generalized split-bf16 HGEMM ----------------
// C[z] = [relu](A[z] @ W[z]^T(n-major) + bias). Tile MTxNTx32, 4 warps, 2-stage cp.async.
// MODE 0: C fp32 +bias. MODE 1: split bf16 +bias. MODE 2: C fp32, no bias.
// z offsets: off = (z>>4)*ozXb + (z&15)*ozXh.
template<int MT, int NT, int MODE, bool RELU>
__global__ void __launch_bounds__(128, 2)
hgemm(const uint16_t* __restrict__ Ah, const uint16_t* __restrict__ Al,
      const uint32_t* __restrict__ Wh, const uint32_t* __restrict__ Wl,
      const float* __restrict__ bias,
      float* __restrict__ C, uint16_t* __restrict__ Ch, uint16_t* __restrict__ Cl,
      int M, int N, int K, int sA, int sWw, int sC,
      size_t ozAb, size_t ozAh, size_t ozWb, size_t ozWh, size_t ozCb, size_t ozCh) {
    constexpr int ALO  = MT * 80;        // bytes: lo plane offset within A region
    constexpr int WOFF = 2 * MT * 80;    // W region start
    constexpr int WLO  = NT * 80;
    constexpr int STG  = 2 * MT * 80 + 2 * NT * 80;

    extern __shared__ char smc[];
    const uint32_t smb = smem_u32(smc);
    const int tid  = threadIdx.x;
    const int lane = tid & 31, warp = tid >> 5;
    const int wm   = (MT == 256) ? warp * 64 : (warp >> 1) * 64;
    const int wn   = (MT == 256) ? 0         : (warp & 1) * 64;
    const int group = lane >> 2, quad = lane & 3;
    const int row0 = blockIdx.y * MT;
    const int col0 = blockIdx.x * NT;

    const int z = blockIdx.z, zb = z >> 4, zh = z & 15;
    Ah += zb * ozAb + zh * ozAh;
    Al += zb * ozAb + zh * ozAh;
    Wh += zb * ozWb + zh * ozWh;
    Wl += zb * ozWb + zh * ozWh;
    const size_t czoff = zb * ozCb + zh * ozCh;

    const int sub = lane >> 3, rr = lane & 7;
    const uint32_t aOff = ((wm + (sub & 1) * 8 + rr) * 40 + (sub >> 1) * 8) * 2;
    const uint32_t wOff = WOFF + ((wn + (sub >> 1) * 8 + rr) * 20 + (sub & 1) * 4) * 4;

    float acc[4][8][4];
#pragma unroll
    for (int i = 0; i < 4; i++)
#pragma unroll
        for (int j = 0; j < 8; j++)
#pragma unroll
            for (int e = 0; e < 4; e++) acc[i][j][e] = 0.f;

    const int iters = K >> 5;

    auto fill = [&](int stage, int k0) {
        uint32_t sb = smb + stage * STG;
#pragma unroll
        for (int i = 0; i < MT / 32; i++) {
            int c = tid + i * 128;
            int row = c >> 2, kc = c & 3;
            size_t g = (size_t)(row0 + row) * sA + k0 + kc * 8;
            uint32_t so = sb + row * 80 + kc * 16;
            cp16(so, Ah + g);
            cp16(so + ALO, Al + g);
        }
        const int k2b = k0 >> 1;
#pragma unroll
        for (int i = 0; i < NT / 32; i++) {
            int c = tid + i * 128;
            int row = c >> 2, ch = c & 3;
            size_t g = (size_t)(col0 + row) * sWw + k2b + ch * 4;
            uint32_t so = sb + WOFF + row * 80 + ch * 16;
            cp16(so, Wh + g);
            cp16(so + WLO, Wl + g);
        }
    };

    auto compute = [&](int stage) {
        const uint32_t aBase = smb + stage * STG + aOff;
        const uint32_t wBase = smb + stage * STG + wOff;
#pragma unroll
        for (int ks = 0; ks < 2; ks++) {
            uint32_t wh_[4][4], wl_[4][4];
#pragma unroll
            for (int p = 0; p < 4; p++) {
                LDSM4(wh_[p][0], wh_[p][1], wh_[p][2], wh_[p][3], wBase + p * 1280 + ks * 32);
                LDSM4(wl_[p][0], wl_[p][1], wl_[p][2], wl_[p][3], wBase + WLO + p * 1280 + ks * 32);
            }
#pragma unroll
            for (int mt = 0; mt < 4; mt++) {
                uint32_t ah[4], al[4];
                LDSM4(ah[0], ah[1], ah[2], ah[3], aBase + mt * 1280 + ks * 32);
                LDSM4(al[0], al[1], al[2], al[3], aBase + ALO + mt * 1280 + ks * 32);
#pragma unroll
                for (int nt = 0; nt < 8; nt++) MMA_BF16(acc[mt][nt], ah, (&wh_[nt >> 1][(nt & 1) * 2]));
#pragma unroll
                for (int nt = 0; nt < 8; nt++) MMA_BF16(acc[mt][nt], al, (&wh_[nt >> 1][(nt & 1) * 2]));
#pragma unroll
                for (int nt = 0; nt < 8; nt++) MMA_BF16(acc[mt][nt], ah, (&wl_[nt >> 1][(nt & 1) * 2]));
            }
        }
    };

    fill(0, 0); cp_commit();

    for (int it = 0; it < iters; ++it) {
        if (it + 1 < iters) { fill((it + 1) & 1, (it + 1) * 32); cp_commit(); cp_wait<1>(); }
        else cp_wait<0>();
        __syncthreads();
        compute(it & 1);
        __syncthreads();
    }

    // ---- epilogue ----
#pragma unroll
    for (int mt = 0; mt < 4; mt++) {
        int r = row0 + wm + mt * 16 + group;
#pragma unroll
        for (int nt = 0; nt < 8; nt++) {
            int c  = col0 + wn + nt * 8 + quad * 2;
            float b0 = 0.f, b1 = 0.f;
            if (MODE != 2) { b0 = bias[c]; b1 = bias[c + 1]; }
            float v0 = acc[mt][nt][0] + b0;
            float v1 = acc[mt][nt][1] + b1;
            float v2 = acc[mt][nt][2] + b0;
            float v3 = acc[mt][nt][3] + b1;
            if (RELU) {
                v0 = fmaxf(v0, 0.f); v1 = fmaxf(v1, 0.f);
                v2 = fmaxf(v2, 0.f); v3 = fmaxf(v3, 0.f);
            }
            if (MODE == 1) {
                uint32_t* ChW = (uint32_t*)Ch;
                uint32_t* ClW = (uint32_t*)Cl;
                size_t i0 = (czoff + (size_t)r * sC + c) >> 1;
                size_t i1 = (czoff + (size_t)(r + 8) * sC + c) >> 1;
                ChW[i0] = pack_hi(v0, v1); ClW[i0] = pack_lo(v0, v1);
                ChW[i1] = pack_hi(v2, v3); ClW[i1] = pack_lo(v2, v3);
            } else {
                *(float2*)&C[czoff + (size_t)r * sC + c]       = make_float2(v0, v1);
                *(float2*)&C[czoff + (size_t)(r + 8) * sC + c] = make_float2(v2, v3);
            }
        }
    }
}

// ---------------- masked softmax: read g_s fp32, write split-bf16 probs ----------------
__global__ void __launch_bounds__(256) softmax_kernel(const int* __restrict__ smask,
                                                      const int* __restrict__ graph) {
    const int warp = threadIdx.x >> 5, lane = threadIdx.x & 31;
    const int r = blockIdx.x * 8 + warp;
    const int b = r >> 12;
    const int q = r & (TTOK - 1);
    const float* row = g_s + (size_t)r * TTOK;
    const int* km = smask + b * TTOK;
    const int* gm = graph + ((size_t)b * TTOK + q) * TTOK;
    const float NEGF = -4294967295.0f;

    float v[8];
    float m = -3.4e38f;
#pragma unroll
    for (int j = 0; j < 8; j++) {
        int c = lane + j * 32;
        float s = row[c] * 0.125f;
        if (!(km[c] > 0 && gm[c] > 0)) s = NEGF;
        v[j] = s;
        m = fmaxf(m, s);
    }
#pragma unroll
    for (int off = 16; off >= 1; off >>= 1)
        m = fmaxf(m, __shfl_xor_sync(0xffffffffu, m, off));
    float sum = 0.f;
#pragma unroll
    for (int j = 0; j < 8; j++) {
        v[j] = expf(v[j] - m);
        sum += v[j];
    }
#pragma unroll
    for (int off = 16; off >= 1; off >>= 1)
        sum += __shfl_xor_sync(0xffffffffu, sum, off);
    float qs = (float)km[q];
    float inv = qs / sum;
#pragma unroll
    for (int j = 0; j < 8; j++) {
        int c = lane + j * 32;
        float p = v[j] * inv;
        g_ph[(size_t)r * TTOK + c] = hi16(p);
        g_pl[(size_t)r * TTOK + c] = lo16(p);
    }
}

// ---------------- residual + layernorm (+ split write) ----------------
__global__ void __launch_bounds__(256) ln_res(const float* __restrict__ addsrc,
                                              const float* __restrict__ gam,
                                              const float* __restrict__ bet) {
    const int row = blockIdx.x;
    const int tid = threadIdx.x;
    const int warp = tid >> 5, lane = tid & 31;
    float* xr = g_x + (size_t)row * DD;
    const float* ar = addsrc + (size_t)row * DD;
    __shared__ float red[8];

    float vals[4];
    float s = 0.f;
#pragma unroll
    for (int j = 0; j < 4; j++) {
        int c = tid + j * 256;
        vals[j] = xr[c] + ar[c];
        s += vals[j];
    }
#pragma unroll
    for (int off = 16; off >= 1; off >>= 1) s += __shfl_xor_sync(0xffffffffu, s, off);
    if (lane == 0) red[warp] = s;
    __syncthreads();
    float tot = 0.f;
#pragma unroll
    for (int w = 0; w < 8; w++) tot += red[w];
    const float mean = tot * (1.f / 1024.f);
    __syncthreads();

    float vs = 0.f;
#pragma unroll
    for (int j = 0; j < 4; j++) {
        float d = vals[j] - mean;
        vs += d * d;
    }
#pragma unroll
    for (int off = 16; off >= 1; off >>= 1) vs += __shfl_xor_sync(0xffffffffu, vs, off);
    if (lane == 0) red[warp] = vs;
    __syncthreads();
    float tot2 = 0.f;
#pragma unroll
    for (int w = 0; w < 8; w++) tot2 += red[w];
    const float var = tot2 * (1.f / 1024.f);
    const float rstd = rsqrtf(var + 1e-8f);

#pragma unroll
    for (int j = 0; j < 4; j++) {
        int c = tid + j * 256;
        float v = (vals[j] - mean) * rstd * gam[c] + bet[c];
        xr[c] = v;
        g_xh[(size_t)row * DD + c] = hi16(v);
        g_xl[(size_t)row * DD + c] = lo16(v);
    }
}

// ---------------- host orchestration ----------------
extern "C" void kernel_launch(void* const* d_in, const int* in_sizes, int n_in,
                              void* d_out, int out_size) {
    const int*   ids   = (const int*)d_in[0];
    const int*   smask = (const int*)d_in[1];
    const int*   graph = (const int*)d_in[2];
    const float* emb   = (const float*)d_in[3];
    const float* w1    = (const float*)d_in[4];
    const float* b1    = (const float*)d_in[5];
    const float* w2    = (const float*)d_in[6];
    const float* b2    = (const float*)d_in[7];
    const float* pos   = (const float*)d_in[8];
    const float* wq    = (const float*)d_in[9];
    const float* bq    = (const float*)d_in[10];
    const float* wk    = (const float*)d_in[11];
    const float* bk    = (const float*)d_in[12];
    const float* wv    = (const float*)d_in[13];
    const float* bv    = (const float*)d_in[14];
    const float* ln1g  = (const float*)d_in[15];
    const float* ln1b  = (const float*)d_in[16];
    const float* fw1   = (const float*)d_in[17];
    const float* fb1   = (const float*)d_in[18];
    const float* fw2   = (const float*)d_in[19];
    const float* fb2   = (const float*)d_in[20];
    const float* ln2g  = (const float*)d_in[21];
    const float* ln2b  = (const float*)d_in[22];

    float *x, *o, *s, *bqkvP;
    uint16_t *xeh, *xel, *xh, *xl, *h1h, *h1l, *ffh, *ffl, *qkvh, *qkvl, *ph, *pl;
    uint32_t *wh, *wl, *vth, *vtl;
    cudaGetSymbolAddress((void**)&x,    g_x);
    cudaGetSymbolAddress((void**)&o,    g_o);
    cudaGetSymbolAddress((void**)&s,    g_s);
    cudaGetSymbolAddress((void**)&bqkvP,g_bqkv);
    cudaGetSymbolAddress((void**)&xeh,  g_xeh);
    cudaGetSymbolAddress((void**)&xel,  g_xel);
    cudaGetSymbolAddress((void**)&xh,   g_xh);
    cudaGetSymbolAddress((void**)&xl,   g_xl);
    cudaGetSymbolAddress((void**)&h1h,  g_h1h);
    cudaGetSymbolAddress((void**)&h1l,  g_h1l);
    cudaGetSymbolAddress((void**)&ffh,  g_ffh);
    cudaGetSymbolAddress((void**)&ffl,  g_ffl);
    cudaGetSymbolAddress((void**)&qkvh, g_qkvh);
    cudaGetSymbolAddress((void**)&qkvl, g_qkvl);
    cudaGetSymbolAddress((void**)&ph,   g_ph);
    cudaGetSymbolAddress((void**)&pl,   g_pl);
    cudaGetSymbolAddress((void**)&vth,  g_vth);
    cudaGetSymbolAddress((void**)&vtl,  g_vtl);
    cudaGetSymbolAddress((void**)&wh,   g_wh);
    cudaGetSymbolAddress((void**)&wl,   g_wl);

    const int SM128 = 2 * (2 * 128 * 80 + 2 * 128 * 80);   // 81920
    const int SM256 = 2 * (2 * 256 * 80 + 2 * 64 * 80);    // 102400
    cudaFuncSetAttribute(hgemm<128,128,0,false>, cudaFuncAttributeMaxDynamicSharedMemorySize, SM128);
    cudaFuncSetAttribute(hgemm<128,128,1,true >, cudaFuncAttributeMaxDynamicSharedMemorySize, SM128);
    cudaFuncSetAttribute(hgemm<128,128,2,false>, cudaFuncAttributeMaxDynamicSharedMemorySize, SM128);
    cudaFuncSetAttribute(hgemm<256,64,2,false>,  cudaFuncAttributeMaxDynamicSharedMemorySize, SM256);

    // launches 1-3 prep; launch #4 = hgemm (profiled)
    embed_gather<<<(NTOK * GDIM + 255) / 256, 256>>>(ids, emb);                                        // 1
    conv_xe<<<(NTOK * GPAD + 255) / 256, 256>>>();                                                     // 2
    pack_wt<<<dim3(MLPH / 32, GPAD / 64), 256>>>(w1, wh + OFF_MLP1, wl + OFF_MLP1, GDIM, MLPH, GPAD);  // 3
    hgemm<128,128,1,true><<<dim3(MLPH / 128, NTOK / 128, 1), 128, SM128>>>(                            // 4 <- profiled
        xeh, xel, wh + OFF_MLP1, wl + OFF_MLP1, b1, nullptr, h1h, h1l,
        NTOK, MLPH, GPAD, GPAD, GPAD / 2, MLPH, 0, 0, 0, 0, 0, 0);
    pack_wt<<<dim3(DD / 32, MLPH / 64), 256>>>(w2, wh + OFF_MLP2, wl + OFF_MLP2, MLPH, DD, MLPH);
    hgemm<128,128,0,false><<<dim3(DD / 128, NTOK / 128, 1), 128, SM128>>>(
        h1h, h1l, wh + OFF_MLP2, wl + OFF_MLP2, b2, x, nullptr, nullptr,
        NTOK, DD, MLPH, MLPH, MLPH / 2, DD, 0, 0, 0, 0, 0, 0);
    add_pos<<<(NTOK * DD) / 256, 256>>>(pos);

    for (int i = 0; i < NBLK; i++) {
        size_t oq = OFF_QKV + (size_t)i * QKV_BLK;
        pack_wt<<<dim3(DD / 32, DD / 64), 256>>>(wq + (size_t)i * DD * DD, wh + oq,                  wl + oq,                  DD, DD, DD);
        pack_wt<<<dim3(DD / 32, DD / 64), 256>>>(wk + (size_t)i * DD * DD, wh + oq + (size_t)DD * DD / 2, wl + oq + (size_t)DD * DD / 2, DD, DD, DD);
        pack_wt<<<dim3(DD / 32, DD / 64), 256>>>(wv + (size_t)i * DD * DD, wh + oq + (size_t)DD * DD,     wl + oq + (size_t)DD * DD,     DD, DD, DD);
        size_t o1 = OFF_FF1 + (size_t)i * FF1_BLK;
        size_t o2 = OFF_FF2 + (size_t)i * FF2_BLK;
        pack_wt<<<dim3(FFH / 32, DD / 64), 256>>>(fw1 + (size_t)i * DD * FFH, wh + o1, wl + o1, DD, FFH, DD);
        pack_wt<<<dim3(DD / 32, FFH / 64), 256>>>(fw2 + (size_t)i * FFH * DD, wh + o2, wl + o2, FFH, DD, FFH);
    }
    pack_bias<<<(NBLK * QKVW + 255) / 256, 256>>>(bq, bk, bv);

    for (int i = 0; i < NBLK; i++) {
        size_t oq = OFF_QKV + (size_t)i * QKV_BLK;
        // fused QKV -> split bf16
        hgemm<128,128,1,true><<<dim3(QKVW / 128, NTOK / 128, 1), 128, SM128>>>(
            xh, xl, wh + oq, wl + oq, bqkvP + i * QKVW, nullptr, qkvh, qkvl,
            NTOK, QKVW, DD, DD, DD / 2, QKVW, 0, 0, 0, 0, 0, 0);

        v_trans<<<dim3(4, BB * HH), 256>>>();

        // scores: S[z][q][key] = Q.K^T  (z = b*16+h)
        hgemm<128,128,2,false><<<dim3(2, 2, BB * HH), 128, SM128>>>(
            qkvh, qkvl, (uint32_t*)qkvh + DD / 2, (uint32_t*)qkvl + DD / 2, nullptr,
            s, nullptr, nullptr,
            TTOK, TTOK, DH, QKVW, QKVW / 2, TTOK,
            (size_t)TTOK * QKVW, DH, (size_t)TTOK * QKVW / 2, DH / 2,
            (size_t)HH * TTOK * TTOK, (size_t)TTOK * TTOK);

        softmax_kernel<<<(BB * HH * TTOK) / 8, 256>>>(smask, graph);

        // O = P @ V  via V^T (n-major)
        hgemm<256,64,2,false><<<dim3(1, 1, BB * HH), 128, SM256>>>(
            ph, pl, vth, vtl, nullptr, o, nullptr, nullptr,
            TTOK, DH, TTOK, TTOK, TTOK / 2, DD,
            (size_t)HH * TTOK * TTOK, (size_t)TTOK * TTOK,
            (size_t)HH * DH * TTOK / 2, (size_t)DH * TTOK / 2,
            (size_t)TTOK * DD, DH);

        ln_res<<<NTOK, 256>>>(o, ln1g + i * DD, ln1b + i * DD);

        size_t o1 = OFF_FF1 + (size_t)i * FF1_BLK;
        size_t o2 = OFF_FF2 + (size_t)i * FF2_BLK;
        hgemm<128,128,1,true><<<dim3(FFH / 128, NTOK / 128, 1), 128, SM128>>>(
            xh, xl, wh + o1, wl + o1, fb1 + i * FFH, nullptr, ffh, ffl,
            NTOK, FFH, DD, DD, DD / 2, FFH, 0, 0, 0, 0, 0, 0);
        hgemm<128,128,0,false><<<dim3(DD / 128, NTOK / 128, 1), 128, SM128>>>(
            ffh, ffl, wh + o2, wl + o2, fb2 + i * DD, o, nullptr, nullptr,
            NTOK, DD, FFH, FFH, FFH / 2, DD, 0, 0, 0, 0, 0, 0);
        ln_res<<<NTOK, 256>>>(o, ln2g + i * DD, ln2b + i * DD);
    }

    cudaMemcpyAsync(d_out, x, sizeof(float) * NTOK * DD, cudaMemcpyDeviceToDevice);
}